// round 12
// baseline (speedup 1.0000x reference)
#include <cuda_runtime.h>
#include <cuda_fp16.h>
#include <math.h>

// Problem constants
#define BB   8
#define TT   4096
#define DD   1024
#define NTOK (BB*TT)          // 32768
#define K2   (2*DD)           // 2048
#define NCHK 8
#define CHKT 512

using u32 = unsigned int;
using u64 = unsigned long long;

// ---------------- scratch (static device globals: allowed) ----------------
__device__ float g_spart[8 * NTOK];
__device__ float g_e[NTOK];
__device__ float g_P[BB * NCHK * DD];     // per-chunk partial num sums
__device__ float g_den0[BB * NCHK];       // exclusive prefix of chunk e-sums
__device__ __half g_X16[(size_t)NTOK * DD];  // X fp16
__device__ __half g_C16[(size_t)NTOK * DD];  // ctx fp16
__device__ __half g_W1[(size_t)DD * DD];     // W1 fp16
__device__ __half g_Wc[(size_t)DD * K2];     // Wc fp16

// ---------------- helpers ----------------
__device__ __forceinline__ u32 smem_u32(const void* p) {
    u32 a;
    asm("{ .reg .u64 t; cvta.to.shared.u64 t, %1; cvt.u32.u64 %0, t; }" : "=r"(a) : "l"(p));
    return a;
}
__device__ __forceinline__ void cp16(u32 dst, const void* src) {
    asm volatile("cp.async.cg.shared.global [%0], [%1], 16;" :: "r"(dst), "l"(src));
}
#define CP_COMMIT() asm volatile("cp.async.commit_group;" ::: "memory")
#define CP_WAIT0()  asm volatile("cp.async.wait_group 0;" ::: "memory")

__device__ __forceinline__ void ldsm4(u32* r, u32 addr) {
    asm volatile("ldmatrix.sync.aligned.m8n8.x4.shared.b16 {%0,%1,%2,%3}, [%4];"
                 : "=r"(r[0]), "=r"(r[1]), "=r"(r[2]), "=r"(r[3]) : "r"(addr));
}
__device__ __forceinline__ void hmma(float* c, const u32* a, u32 b0, u32 b1) {
    asm("mma.sync.aligned.m16n8k16.row.col.f32.f16.f16.f32 "
        "{%0,%1,%2,%3}, {%4,%5,%6,%7}, {%8,%9}, {%0,%1,%2,%3};"
        : "+f"(c[0]), "+f"(c[1]), "+f"(c[2]), "+f"(c[3])
        : "r"(a[0]), "r"(a[1]), "r"(a[2]), "r"(a[3]), "r"(b0), "r"(b1));
}
// accurate fast tanh: 1 - 2/(1+e^{2x})
__device__ __forceinline__ float tanh_acc(float x) {
    float e, r;
    asm("ex2.approx.f32 %0, %1;" : "=f"(e) : "f"(x * 2.885390081777927f));
    asm("rcp.approx.f32 %0, %1;" : "=f"(r) : "f"(e + 1.0f));
    return fmaf(-2.0f, r, 1.0f);
}

// ---------------- tile geometry ----------------
// CTA tile 256(M) x 128(N), K-chunk 64. 8 warps (4x2), warp tile 64x64.
#define A_TILE   32768                 // 256 x 64 fp16
#define B_TILE   16384                 // 128 x 64 fp16
#define STAGE_B  (A_TILE + B_TILE)     // 48 KB
#define DYN_B    (2*STAGE_B + 1024)

// per-lane fragment addressing constants
struct LaneCtx {
    u32 raoff[4];   // A row offsets per 16-row m tile (warp covers m=64)
    u32 rboff[4];   // B row offsets per 16-row n-pair (warp covers n=64)
    u32 colk[4];    // swizzled column offset per k16
};
__device__ __forceinline__ LaneCtx make_ctx(int tid) {
    LaneCtx cx;
    const int lane = tid & 31;
    const int wm = (tid >> 5) >> 1;        // 0..3
    const int wn = (tid >> 5) & 1;         // 0..1
    const int quad = lane >> 3, r8 = lane & 7;
    const int cb = (quad >> 1) << 4;
    const int rsel = ((quad & 1) << 3) + r8;
    const u32 xsw = (u32)(r8 << 4);
#pragma unroll
    for (int mi = 0; mi < 4; mi++) cx.raoff[mi] = (u32)((wm*64 + mi*16 + rsel) * 128);
#pragma unroll
    for (int p = 0; p < 4; p++)    cx.rboff[p]  = (u32)((wn*64 + p*16 + rsel) * 128);
#pragma unroll
    for (int k = 0; k < 4; k++)    cx.colk[k]   = ((u32)(cb + k*32)) ^ xsw;
    return cx;
}

// precomputed load offsets (global elt offset + swizzled smem offset)
struct LoadOff {
    u32 ag[8], as_[8];   // A tile: 8 cp16 per thread (256 rows)
    u32 bg[4], bs_[4];   // B tile: 4 cp16 per thread (128 rows)
};
__device__ __forceinline__ LoadOff make_loff(int tid, int bstride) {
    LoadOff lo;
#pragma unroll
    for (int i = 0; i < 8; i++) {
        int idx = tid + (i << 8);
        int row = idx >> 3, c8 = (idx & 7) << 3;
        lo.ag[i] = (u32)(row * DD + c8);
        u32 off = (u32)(row * 128 + (c8 << 1));
        lo.as_[i] = off ^ ((off >> 3) & 0x70u);
    }
#pragma unroll
    for (int i = 0; i < 4; i++) {
        int idx = tid + (i << 8);
        int row = idx >> 3, c8 = (idx & 7) << 3;
        lo.bg[i] = (u32)(row * bstride + c8);
        u32 off = (u32)(row * 128 + (c8 << 1));
        lo.bs_[i] = off ^ ((off >> 3) & 0x70u);
    }
    return lo;
}

__device__ __forceinline__ void load_stage(u32 sb2, const LoadOff& lo,
                                           const __half* pA, const __half* pB) {
#pragma unroll
    for (int i = 0; i < 8; i++)
        cp16(sb2 + lo.as_[i], pA + lo.ag[i]);
#pragma unroll
    for (int i = 0; i < 4; i++)
        cp16(sb2 + A_TILE + lo.bs_[i], pB + lo.bg[i]);
}

// one k16 step of the 64x64 warp tile (8 ldsm -> 32 HMMA)
__device__ __forceinline__ void mma_k16(float acc[4][8][4], const LaneCtx& cx,
                                        u32 stage, int k16) {
    const u32 Ab = stage, Bb = stage + A_TILE;
    const u32 c = cx.colk[k16];
    u32 b[4][4];
#pragma unroll
    for (int p = 0; p < 4; p++) ldsm4(b[p], Bb + cx.rboff[p] + c);
    u32 a[4][4];
#pragma unroll
    for (int mi = 0; mi < 4; mi++) ldsm4(a[mi], Ab + cx.raoff[mi] + c);
#pragma unroll
    for (int mi = 0; mi < 4; mi++)
#pragma unroll
        for (int ni = 0; ni < 8; ni++) {
            const int p = ni >> 1, s = ni & 1;
            hmma(acc[mi][ni], a[mi], b[p][s], b[p][s+2]);
        }
}

// =====================================================================
// GEMM 1: scores. D[n,e] = X·W1^T; epilogue: spart = sum_e tanh(D+b1)*w2
// grid = (e-tiles=8, n-tiles=128); consecutive blocks share the A tile.
// Software-pipelined: cp.async issue overlapped with MMA, 1 barrier/chunk.
// =====================================================================
__global__ __launch_bounds__(256)
void gemm_score_mma(const float* __restrict__ b1, const float* __restrict__ w2)
{
    extern __shared__ char dyn[];
    __shared__ float red[256][2];
    const int tid = threadIdx.x;
    const int e0 = blockIdx.x * 128;
    const int n0 = blockIdx.y * 256;
    const u32 dynb = smem_u32(dyn);
    const u32 base = (dynb + 1023u) & ~1023u;

    const __half* Ap = g_X16 + (size_t)n0 * DD;
    const __half* Bp = g_W1  + (size_t)e0 * DD;

    const LaneCtx cx = make_ctx(tid);
    const LoadOff lo = make_loff(tid, DD);
    float acc[4][8][4];
#pragma unroll
    for (int i = 0; i < 4; i++)
#pragma unroll
        for (int j = 0; j < 8; j++)
#pragma unroll
            for (int q = 0; q < 4; q++) acc[i][j][q] = 0.f;

    load_stage(base, lo, Ap, Bp);
    CP_COMMIT();

    const int NCH = DD / 64;   // 16
    for (int kt = 0; kt < NCH; kt++) {
        const u32 cur = base + ((u32)(kt & 1)) * STAGE_B;
        CP_WAIT0();          // cur stage resident
        __syncthreads();     // all warps past mma(kt-1) before overwriting next buf
        mma_k16(acc, cx, cur, 0);
        mma_k16(acc, cx, cur, 1);
        if (kt + 1 < NCH) {
            const u32 nxt = base + ((u32)((kt+1) & 1)) * STAGE_B;
            const int ko = (kt + 1) * 64;
            load_stage(nxt, lo, Ap + ko, Bp + ko);
            CP_COMMIT();
        }
        mma_k16(acc, cx, cur, 2);
        mma_k16(acc, cx, cur, 3);
    }

    // epilogue: tanh(D+b1)*w2, reduce over the CTA's 128 e-cols
    const int lane = tid & 31;
    const int wm = (tid >> 5) >> 1, wn = (tid >> 5) & 1;
    float b1x[8], b1y[8], w2x[8], w2y[8];
#pragma unroll
    for (int ni = 0; ni < 8; ni++) {
        const int col = e0 + wn*64 + ni*8 + 2*(lane & 3);
        float2 bv = *(const float2*)(b1 + col);
        float2 wv = *(const float2*)(w2 + col);
        b1x[ni] = bv.x; b1y[ni] = bv.y; w2x[ni] = wv.x; w2y[ni] = wv.y;
    }
#pragma unroll
    for (int mi = 0; mi < 4; mi++)
#pragma unroll
        for (int h2 = 0; h2 < 2; h2++) {
            float s = 0.f;
#pragma unroll
            for (int ni = 0; ni < 8; ni++) {
                s += tanh_acc(acc[mi][ni][h2*2+0] + b1x[ni]) * w2x[ni];
                s += tanh_acc(acc[mi][ni][h2*2+1] + b1y[ni]) * w2y[ni];
            }
            s += __shfl_xor_sync(0xffffffffu, s, 1);
            s += __shfl_xor_sync(0xffffffffu, s, 2);
            if ((lane & 3) == 0)
                red[wm*64 + mi*16 + h2*8 + (lane >> 2)][wn] = s;
        }
    __syncthreads();
    g_spart[(size_t)blockIdx.x * NTOK + n0 + tid] = red[tid][0] + red[tid][1];
}

// =====================================================================
// Kernel 2: per-batch max + e = exp(s + b2 - m); also per-chunk e sums
// =====================================================================
__global__ void softmax_prep(const float* __restrict__ b2)
{
    const int b = blockIdx.x, tid = threadIdx.x;   // 256 threads
    const int lane = tid & 31;
    float vloc[16];
    float mx = -INFINITY;
    const float b2v = b2[0];
#pragma unroll
    for (int i = 0; i < 16; i++) {
        int t = tid + i * 256;
        float s = 0.f;
#pragma unroll
        for (int eb = 0; eb < 8; eb++) s += g_spart[(size_t)eb * NTOK + b * TT + t];
        s += b2v;
        vloc[i] = s;
        mx = fmaxf(mx, s);
    }
    __shared__ float sm[256];
    __shared__ float dsum[NCHK];
    sm[tid] = mx;
    if (tid < NCHK) dsum[tid] = 0.f;
    __syncthreads();
    for (int off = 128; off > 0; off >>= 1) {
        if (tid < off) sm[tid] = fmaxf(sm[tid], sm[tid + off]);
        __syncthreads();
    }
    float m = sm[0];
    float eloc[16];
#pragma unroll
    for (int i = 0; i < 16; i++) {
        int t = tid + i * 256;
        eloc[i] = expf(vloc[i] - m);
        g_e[b * TT + t] = eloc[i];
    }
#pragma unroll
    for (int c = 0; c < NCHK; c++) {
        float v = eloc[2*c] + eloc[2*c+1];
#pragma unroll
        for (int off = 16; off > 0; off >>= 1)
            v += __shfl_xor_sync(0xffffffffu, v, off);
        if (lane == 0) atomicAdd(&dsum[c], v);
    }
    __syncthreads();
    if (tid == 0) {
        float run = 0.f;
#pragma unroll
        for (int c = 0; c < NCHK; c++) { g_den0[b * NCHK + c] = run; run += dsum[c]; }
    }
}

// =====================================================================
// Scan pass A: per-chunk partial sums  P[b,chunk,d] = sum_{t in chunk} e*x
// (reads fp16 X: half the traffic; error far below ctx fp16 rounding)
// =====================================================================
__global__ void scan_part()
{
    const int b = blockIdx.y, chunk = blockIdx.z;
    const int d = blockIdx.x * 128 + threadIdx.x;
    const __half* xb = g_X16 + (size_t)b * TT * DD + (size_t)chunk * CHKT * DD + d;
    __shared__ float es[CHKT];
#pragma unroll
    for (int i = 0; i < CHKT/128; i++)
        es[threadIdx.x + i*128] = g_e[b * TT + chunk * CHKT + threadIdx.x + i*128];
    __syncthreads();
    float P = 0.f;
#pragma unroll 8
    for (int tt = 0; tt < CHKT; ++tt)
        P = fmaf(es[tt], __half2float(xb[(size_t)tt * DD]), P);
    g_P[(b * NCHK + chunk) * DD + d] = P;
}

// Exclusive prefix of P over chunks (in place). grid BB, 1024 threads.
__global__ void prefP()
{
    const int b = blockIdx.x, d = threadIdx.x;
    float run = 0.f;
#pragma unroll
    for (int c = 0; c < NCHK; c++) {
        int idx = (b * NCHK + c) * DD + d;
        float t = (c < NCHK-1) ? g_P[idx] : 0.f;
        g_P[idx] = run;
        run += t;
    }
}

// =====================================================================
// Scan pass B: local cumsum + prefix offsets; emits ctx as fp16.
// =====================================================================
__global__ void scan_final()
{
    const int b = blockIdx.y, chunk = blockIdx.z;
    const int d = blockIdx.x * 128 + threadIdx.x;
    const size_t rowoff = (size_t)b * TT * DD + (size_t)chunk * CHKT * DD + d;
    const __half* xb = g_X16 + rowoff;
    __half* cp = g_C16 + rowoff;

    __shared__ float es[CHKT];
#pragma unroll
    for (int i = 0; i < CHKT/128; i++)
        es[threadIdx.x + i*128] = g_e[b * TT + chunk * CHKT + threadIdx.x + i*128];
    __syncthreads();

    float den = g_den0[b * NCHK + chunk];
    float num = g_P[(b * NCHK + chunk) * DD + d];
#pragma unroll 8
    for (int tt = 0; tt < CHKT; ++tt) {
        float ev = es[tt];
        den += ev;
        num = fmaf(ev, __half2float(xb[(size_t)tt * DD]), num);
        float rcp;
        asm("rcp.approx.f32 %0, %1;" : "=f"(rcp) : "f"(den));
        cp[(size_t)tt * DD] = __float2half_rn(num * rcp);
    }
}

// =====================================================================
// GEMM 2: out = tanh([ctx,x]·Wc^T + bc); K split ctx(0:1024)/x(1024:2048)
// =====================================================================
__global__ __launch_bounds__(256)
void gemm_out_mma(const float* __restrict__ bc, float* __restrict__ out)
{
    extern __shared__ char dyn[];
    const int tid = threadIdx.x;
    const int d0 = blockIdx.x * 128;
    const int n0 = blockIdx.y * 256;
    const u32 dynb = smem_u32(dyn);
    const u32 base = (dynb + 1023u) & ~1023u;

    const __half* Bp = g_Wc + (size_t)d0 * K2;

    const LaneCtx cx = make_ctx(tid);
    const LoadOff lo = make_loff(tid, K2);
    float acc[4][8][4];
#pragma unroll
    for (int i = 0; i < 4; i++)
#pragma unroll
        for (int j = 0; j < 8; j++)
#pragma unroll
            for (int q = 0; q < 4; q++) acc[i][j][q] = 0.f;

    auto getA = [&](int ko) -> const __half* {
        return (ko < DD) ? (g_C16 + (size_t)n0 * DD + ko)
                         : (g_X16 + (size_t)n0 * DD + (ko - DD));
    };

    load_stage(base, lo, getA(0), Bp);
    CP_COMMIT();

    const int NCH = K2 / 64;   // 32
    for (int kt = 0; kt < NCH; kt++) {
        const u32 cur = base + ((u32)(kt & 1)) * STAGE_B;
        CP_WAIT0();
        __syncthreads();
        mma_k16(acc, cx, cur, 0);
        mma_k16(acc, cx, cur, 1);
        if (kt + 1 < NCH) {
            const u32 nxt = base + ((u32)((kt+1) & 1)) * STAGE_B;
            const int ko = (kt + 1) * 64;
            load_stage(nxt, lo, getA(ko), Bp + ko);
            CP_COMMIT();
        }
        mma_k16(acc, cx, cur, 2);
        mma_k16(acc, cx, cur, 3);
    }

    // epilogue: tanh(acc + bc) -> out
    const int lane = tid & 31;
    const int wm = (tid >> 5) >> 1, wn = (tid >> 5) & 1;
#pragma unroll
    for (int ni = 0; ni < 8; ni++) {
        const int colb = d0 + wn*64 + ni*8 + 2*(lane & 3);
        const float2 bcv = *(const float2*)(bc + colb);
#pragma unroll
        for (int mi = 0; mi < 4; mi++) {
            const int row0 = n0 + wm*64 + mi*16 + (lane >> 2);
            float2 o0, o1;
            o0.x = tanh_acc(acc[mi][ni][0] + bcv.x);
            o0.y = tanh_acc(acc[mi][ni][1] + bcv.y);
            o1.x = tanh_acc(acc[mi][ni][2] + bcv.x);
            o1.y = tanh_acc(acc[mi][ni][3] + bcv.y);
            *(float2*)(out + (size_t)row0 * DD + colb) = o0;
            *(float2*)(out + (size_t)(row0 + 8) * DD + colb) = o1;
        }
    }
}

// =====================================================================
// converters: fp32 -> fp16 (round to nearest)
// =====================================================================
struct __align__(8) hf4 { __half v[4]; };

__device__ __forceinline__ void round4h(const float* __restrict__ src,
                                        __half* __restrict__ dst, int i) {
    float4 v = ((const float4*)src)[i];
    hf4 h;
    h.v[0] = __float2half_rn(v.x); h.v[1] = __float2half_rn(v.y);
    h.v[2] = __float2half_rn(v.z); h.v[3] = __float2half_rn(v.w);
    ((hf4*)dst)[i] = h;
}
__global__ void cvt_x(const float* __restrict__ src) {
    int i = blockIdx.x * blockDim.x + threadIdx.x;
    if (i < NTOK * (DD/4)) round4h(src, g_X16, i);
}
__global__ void cvt_w1(const float* __restrict__ src) {
    int i = blockIdx.x * blockDim.x + threadIdx.x;
    if (i < DD * (DD/4)) round4h(src, g_W1, i);
}
__global__ void cvt_wc(const float* __restrict__ src) {
    int i = blockIdx.x * blockDim.x + threadIdx.x;
    if (i < DD * (K2/4)) round4h(src, g_Wc, i);
}

// =====================================================================
extern "C" void kernel_launch(void* const* d_in, const int* in_sizes, int n_in,
                              void* d_out, int out_size)
{
    const float* x  = (const float*)d_in[0];
    const float* W1 = (const float*)d_in[1];
    const float* b1 = (const float*)d_in[2];
    const float* w2 = (const float*)d_in[3];
    const float* b2 = (const float*)d_in[4];
    const float* Wc = (const float*)d_in[5];
    const float* bc = (const float*)d_in[6];
    float* out = (float*)d_out;

    cudaFuncSetAttribute(gemm_score_mma, cudaFuncAttributeMaxDynamicSharedMemorySize, DYN_B);
    cudaFuncSetAttribute(gemm_out_mma,   cudaFuncAttributeMaxDynamicSharedMemorySize, DYN_B);

    cvt_x <<<(NTOK*(DD/4) + 255)/256, 256>>>(x);
    cvt_w1<<<(DD*(DD/4)   + 255)/256, 256>>>(W1);
    cvt_wc<<<(DD*(K2/4)   + 255)/256, 256>>>(Wc);

    dim3 g1(DD / 128, NTOK / 256);      // (8, 128): e-tiles fast, share A
    gemm_score_mma<<<g1, 256, DYN_B>>>(b1, w2);

    softmax_prep<<<BB, 256>>>(b2);

    dim3 gp(DD / 128, BB, NCHK - 1);
    scan_part<<<gp, 128>>>();
    prefP<<<BB, 1024>>>();
    dim3 gf(DD / 128, BB, NCHK);
    scan_final<<<gf, 128>>>();

    dim3 g4(DD / 128, NTOK / 256);      // (8, 128): d-tiles fast
    gemm_out_mma<<<g4, 256, DYN_B>>>(bc, out);
}

// round 13
// speedup vs baseline: 1.2359x; 1.2359x over previous
#include <cuda_runtime.h>
#include <cuda_fp16.h>
#include <math.h>

// Problem constants
#define BB   8
#define TT   4096
#define DD   1024
#define NTOK (BB*TT)          // 32768
#define K2   (2*DD)           // 2048
#define NCHK 8
#define CHKT 512

using u32 = unsigned int;
using u64 = unsigned long long;

// ---------------- scratch (static device globals: allowed) ----------------
__device__ float g_spart[8 * NTOK];
__device__ float g_e[NTOK];
__device__ float g_P[BB * NCHK * DD];     // per-chunk partial num sums
__device__ float g_den0[BB * NCHK];       // exclusive prefix of chunk e-sums
__device__ __half g_X16[(size_t)NTOK * DD];  // X fp16
__device__ __half g_C16[(size_t)NTOK * DD];  // ctx fp16
__device__ __half g_W1[(size_t)DD * DD];     // W1 fp16
__device__ __half g_Wc[(size_t)DD * K2];     // Wc fp16

// ---------------- helpers ----------------
__device__ __forceinline__ u32 smem_u32(const void* p) {
    u32 a;
    asm("{ .reg .u64 t; cvta.to.shared.u64 t, %1; cvt.u32.u64 %0, t; }" : "=r"(a) : "l"(p));
    return a;
}
__device__ __forceinline__ void cp16(u32 dst, const void* src) {
    asm volatile("cp.async.cg.shared.global [%0], [%1], 16;" :: "r"(dst), "l"(src));
}
#define CP_COMMIT() asm volatile("cp.async.commit_group;" ::: "memory")
#define CP_WAIT1()  asm volatile("cp.async.wait_group 1;" ::: "memory")
#define CP_WAIT0()  asm volatile("cp.async.wait_group 0;" ::: "memory")

__device__ __forceinline__ void ldsm4(u32* r, u32 addr) {
    asm volatile("ldmatrix.sync.aligned.m8n8.x4.shared.b16 {%0,%1,%2,%3}, [%4];"
                 : "=r"(r[0]), "=r"(r[1]), "=r"(r[2]), "=r"(r[3]) : "r"(addr));
}
__device__ __forceinline__ void hmma(float* c, const u32* a, u32 b0, u32 b1) {
    asm("mma.sync.aligned.m16n8k16.row.col.f32.f16.f16.f32 "
        "{%0,%1,%2,%3}, {%4,%5,%6,%7}, {%8,%9}, {%0,%1,%2,%3};"
        : "+f"(c[0]), "+f"(c[1]), "+f"(c[2]), "+f"(c[3])
        : "r"(a[0]), "r"(a[1]), "r"(a[2]), "r"(a[3]), "r"(b0), "r"(b1));
}
// accurate fast tanh: 1 - 2/(1+e^{2x})
__device__ __forceinline__ float tanh_acc(float x) {
    float e, r;
    asm("ex2.approx.f32 %0, %1;" : "=f"(e) : "f"(x * 2.885390081777927f));
    asm("rcp.approx.f32 %0, %1;" : "=f"(r) : "f"(e + 1.0f));
    return fmaf(-2.0f, r, 1.0f);
}

// ---------------- tile geometry ----------------
// CTA tile 256(M) x 128(N), K-chunk 64. 16 warps (4x4), warp tile 64x32.
#define A_TILE   32768                 // 256 x 64 fp16
#define B_TILE   16384                 // 128 x 64 fp16
#define STAGE_B  (A_TILE + B_TILE)     // 48 KB
#define DYN_B    (2*STAGE_B + 1024)

// per-lane fragment addressing constants
struct LaneCtx {
    u32 raoff[4];   // A row offsets per 16-row m tile (warp covers m=64)
    u32 rboff[2];   // B row offsets per 16-row n-pair (warp covers n=32)
    u32 colk[4];    // swizzled column offset per k16
};
__device__ __forceinline__ LaneCtx make_ctx(int tid) {
    LaneCtx cx;
    const int lane = tid & 31;
    const int wm = (tid >> 5) >> 2;        // 0..3
    const int wn = (tid >> 5) & 3;         // 0..3
    const int quad = lane >> 3, r8 = lane & 7;
    const int cb = (quad >> 1) << 4;
    const int rsel = ((quad & 1) << 3) + r8;
    const u32 xsw = (u32)(r8 << 4);
#pragma unroll
    for (int mi = 0; mi < 4; mi++) cx.raoff[mi] = (u32)((wm*64 + mi*16 + rsel) * 128);
#pragma unroll
    for (int p = 0; p < 2; p++)    cx.rboff[p]  = (u32)((wn*32 + p*16 + rsel) * 128);
#pragma unroll
    for (int k = 0; k < 4; k++)    cx.colk[k]   = ((u32)(cb + k*32)) ^ xsw;
    return cx;
}

// precomputed load offsets (global elt offset + swizzled smem offset), 512 thr
struct LoadOff {
    u32 ag[4], as_[4];   // A tile: 4 cp16 per thread (256 rows x 64 cols)
    u32 bg[2], bs_[2];   // B tile: 2 cp16 per thread (128 rows x 64 cols)
};
__device__ __forceinline__ LoadOff make_loff(int tid, int bstride) {
    LoadOff lo;
#pragma unroll
    for (int i = 0; i < 4; i++) {
        int idx = tid + (i << 9);
        int row = idx >> 3, c8 = (idx & 7) << 3;
        lo.ag[i] = (u32)(row * DD + c8);
        u32 off = (u32)(row * 128 + (c8 << 1));
        lo.as_[i] = off ^ ((off >> 3) & 0x70u);
    }
#pragma unroll
    for (int i = 0; i < 2; i++) {
        int idx = tid + (i << 9);
        int row = idx >> 3, c8 = (idx & 7) << 3;
        lo.bg[i] = (u32)(row * bstride + c8);
        u32 off = (u32)(row * 128 + (c8 << 1));
        lo.bs_[i] = off ^ ((off >> 3) & 0x70u);
    }
    return lo;
}

__device__ __forceinline__ void load_stage(u32 sb2, const LoadOff& lo,
                                           const __half* pA, const __half* pB) {
#pragma unroll
    for (int i = 0; i < 4; i++)
        cp16(sb2 + lo.as_[i], pA + lo.ag[i]);
#pragma unroll
    for (int i = 0; i < 2; i++)
        cp16(sb2 + A_TILE + lo.bs_[i], pB + lo.bg[i]);
}

// MMA over one resident 64-wide K chunk, warp tile 64x32, single fp16 product.
__device__ __forceinline__ void mma_chunk(float acc[4][4][4], const LaneCtx& cx, u32 stage) {
    const u32 Ab = stage, Bb = stage + A_TILE;
#pragma unroll
    for (int k16 = 0; k16 < 4; k16++) {
        const u32 c = cx.colk[k16];
        u32 b[2][4];
#pragma unroll
        for (int p = 0; p < 2; p++) ldsm4(b[p], Bb + cx.rboff[p] + c);
        u32 a[4][4];
#pragma unroll
        for (int mi = 0; mi < 4; mi++) ldsm4(a[mi], Ab + cx.raoff[mi] + c);
#pragma unroll
        for (int mi = 0; mi < 4; mi++)
#pragma unroll
            for (int ni = 0; ni < 4; ni++) {
                const int p = ni >> 1, s = ni & 1;
                hmma(acc[mi][ni], a[mi], b[p][s], b[p][s+2]);
            }
    }
}

// =====================================================================
// GEMM 1: scores. D[n,e] = X·W1^T; epilogue: spart = sum_e tanh(D+b1)*w2
// grid = (e-tiles=8, n-tiles=128); consecutive blocks share the A tile.
// =====================================================================
__global__ __launch_bounds__(512)
void gemm_score_mma(const float* __restrict__ b1, const float* __restrict__ w2)
{
    extern __shared__ char dyn[];
    __shared__ float red[256][4];
    const int tid = threadIdx.x;
    const int e0 = blockIdx.x * 128;
    const int n0 = blockIdx.y * 256;
    const u32 dynb = smem_u32(dyn);
    const u32 base = (dynb + 1023u) & ~1023u;

    const __half* Ap = g_X16 + (size_t)n0 * DD;
    const __half* Bp = g_W1  + (size_t)e0 * DD;

    const LaneCtx cx = make_ctx(tid);
    const LoadOff lo = make_loff(tid, DD);
    float acc[4][4][4];
#pragma unroll
    for (int i = 0; i < 4; i++)
#pragma unroll
        for (int j = 0; j < 4; j++)
#pragma unroll
            for (int q = 0; q < 4; q++) acc[i][j][q] = 0.f;

    load_stage(base, lo, Ap, Bp);
    CP_COMMIT();

    const int NCH = DD / 64;   // 16
    for (int kt = 0; kt < NCH; kt++) {
        if (kt > 0) __syncthreads();
        if (kt + 1 < NCH) {
            const u32 sb2 = base + ((u32)((kt+1) & 1)) * STAGE_B;
            const int ko = (kt + 1) * 64;
            load_stage(sb2, lo, Ap + ko, Bp + ko);
            CP_COMMIT();
            CP_WAIT1();
        } else {
            CP_WAIT0();
        }
        __syncthreads();
        mma_chunk(acc, cx, base + ((u32)(kt & 1)) * STAGE_B);
    }

    // epilogue: tanh(D+b1)*w2, reduce over the CTA's 128 e-cols
    const int lane = tid & 31;
    const int wm = (tid >> 5) >> 2, wn = (tid >> 5) & 3;
    float b1x[4], b1y[4], w2x[4], w2y[4];
#pragma unroll
    for (int ni = 0; ni < 4; ni++) {
        const int col = e0 + wn*32 + ni*8 + 2*(lane & 3);
        float2 bv = *(const float2*)(b1 + col);
        float2 wv = *(const float2*)(w2 + col);
        b1x[ni] = bv.x; b1y[ni] = bv.y; w2x[ni] = wv.x; w2y[ni] = wv.y;
    }
#pragma unroll
    for (int mi = 0; mi < 4; mi++)
#pragma unroll
        for (int h2 = 0; h2 < 2; h2++) {
            float s = 0.f;
#pragma unroll
            for (int ni = 0; ni < 4; ni++) {
                s += tanh_acc(acc[mi][ni][h2*2+0] + b1x[ni]) * w2x[ni];
                s += tanh_acc(acc[mi][ni][h2*2+1] + b1y[ni]) * w2y[ni];
            }
            s += __shfl_xor_sync(0xffffffffu, s, 1);
            s += __shfl_xor_sync(0xffffffffu, s, 2);
            if ((lane & 3) == 0)
                red[wm*64 + mi*16 + h2*8 + (lane >> 2)][wn] = s;
        }
    __syncthreads();
    if (tid < 256)
        g_spart[(size_t)blockIdx.x * NTOK + n0 + tid] =
            red[tid][0] + red[tid][1] + red[tid][2] + red[tid][3];
}

// =====================================================================
// Kernel 2: per-batch max + e = exp(s + b2 - m); also per-chunk e sums
// =====================================================================
__global__ void softmax_prep(const float* __restrict__ b2)
{
    const int b = blockIdx.x, tid = threadIdx.x;   // 256 threads
    const int lane = tid & 31;
    float vloc[16];
    float mx = -INFINITY;
    const float b2v = b2[0];
#pragma unroll
    for (int i = 0; i < 16; i++) {
        int t = tid + i * 256;
        float s = 0.f;
#pragma unroll
        for (int eb = 0; eb < 8; eb++) s += g_spart[(size_t)eb * NTOK + b * TT + t];
        s += b2v;
        vloc[i] = s;
        mx = fmaxf(mx, s);
    }
    __shared__ float sm[256];
    __shared__ float dsum[NCHK];
    sm[tid] = mx;
    if (tid < NCHK) dsum[tid] = 0.f;
    __syncthreads();
    for (int off = 128; off > 0; off >>= 1) {
        if (tid < off) sm[tid] = fmaxf(sm[tid], sm[tid + off]);
        __syncthreads();
    }
    float m = sm[0];
    float eloc[16];
#pragma unroll
    for (int i = 0; i < 16; i++) {
        int t = tid + i * 256;
        eloc[i] = expf(vloc[i] - m);
        g_e[b * TT + t] = eloc[i];
    }
#pragma unroll
    for (int c = 0; c < NCHK; c++) {
        float v = eloc[2*c] + eloc[2*c+1];
#pragma unroll
        for (int off = 16; off > 0; off >>= 1)
            v += __shfl_xor_sync(0xffffffffu, v, off);
        if (lane == 0) atomicAdd(&dsum[c], v);
    }
    __syncthreads();
    if (tid == 0) {
        float run = 0.f;
#pragma unroll
        for (int c = 0; c < NCHK; c++) { g_den0[b * NCHK + c] = run; run += dsum[c]; }
    }
}

// =====================================================================
// Scan pass A: per-chunk partial sums  P[b,chunk,d] = sum_{t in chunk} e*x
// =====================================================================
__global__ void scan_part(const float* __restrict__ X)
{
    const int b = blockIdx.y, chunk = blockIdx.z;
    const int d = blockIdx.x * 128 + threadIdx.x;
    const float* xb = X + (size_t)b * TT * DD + (size_t)chunk * CHKT * DD + d;
    __shared__ float es[CHKT];
#pragma unroll
    for (int i = 0; i < CHKT/128; i++)
        es[threadIdx.x + i*128] = g_e[b * TT + chunk * CHKT + threadIdx.x + i*128];
    __syncthreads();
    float P = 0.f;
#pragma unroll 8
    for (int tt = 0; tt < CHKT; ++tt)
        P = fmaf(es[tt], xb[(size_t)tt * DD], P);
    g_P[(b * NCHK + chunk) * DD + d] = P;
}

// Exclusive prefix of P over chunks (in place). grid BB, 1024 threads.
__global__ void prefP()
{
    const int b = blockIdx.x, d = threadIdx.x;
    float run = 0.f;
#pragma unroll
    for (int c = 0; c < NCHK; c++) {
        int idx = (b * NCHK + c) * DD + d;
        float t = (c < NCHK-1) ? g_P[idx] : 0.f;
        g_P[idx] = run;
        run += t;
    }
}

// =====================================================================
// Scan pass B: local cumsum + prefix offsets; emits ctx as fp16.
// =====================================================================
__global__ void scan_final(const float* __restrict__ X)
{
    const int b = blockIdx.y, chunk = blockIdx.z;
    const int d = blockIdx.x * 128 + threadIdx.x;
    const size_t rowoff = (size_t)b * TT * DD + (size_t)chunk * CHKT * DD + d;
    const float* xb = X + rowoff;
    __half* cp = g_C16 + rowoff;

    __shared__ float es[CHKT];
#pragma unroll
    for (int i = 0; i < CHKT/128; i++)
        es[threadIdx.x + i*128] = g_e[b * TT + chunk * CHKT + threadIdx.x + i*128];
    __syncthreads();

    float den = g_den0[b * NCHK + chunk];
    float num = g_P[(b * NCHK + chunk) * DD + d];
#pragma unroll 8
    for (int tt = 0; tt < CHKT; ++tt) {
        float ev = es[tt];
        den += ev;
        num = fmaf(ev, xb[(size_t)tt * DD], num);
        float rcp;
        asm("rcp.approx.f32 %0, %1;" : "=f"(rcp) : "f"(den));
        cp[(size_t)tt * DD] = __float2half_rn(num * rcp);
    }
}

// =====================================================================
// GEMM 2: out = tanh([ctx,x]·Wc^T + bc); K split ctx(0:1024)/x(1024:2048)
// =====================================================================
__global__ __launch_bounds__(512)
void gemm_out_mma(const float* __restrict__ bc, float* __restrict__ out)
{
    extern __shared__ char dyn[];
    const int tid = threadIdx.x;
    const int d0 = blockIdx.x * 128;
    const int n0 = blockIdx.y * 256;
    const u32 dynb = smem_u32(dyn);
    const u32 base = (dynb + 1023u) & ~1023u;

    const __half* Bp = g_Wc + (size_t)d0 * K2;

    const LaneCtx cx = make_ctx(tid);
    const LoadOff lo = make_loff(tid, K2);
    float acc[4][4][4];
#pragma unroll
    for (int i = 0; i < 4; i++)
#pragma unroll
        for (int j = 0; j < 4; j++)
#pragma unroll
            for (int q = 0; q < 4; q++) acc[i][j][q] = 0.f;

    auto getA = [&](int ko) -> const __half* {
        return (ko < DD) ? (g_C16 + (size_t)n0 * DD + ko)
                         : (g_X16 + (size_t)n0 * DD + (ko - DD));
    };

    load_stage(base, lo, getA(0), Bp);
    CP_COMMIT();

    const int NCH = K2 / 64;   // 32
    for (int kt = 0; kt < NCH; kt++) {
        if (kt > 0) __syncthreads();
        if (kt + 1 < NCH) {
            const u32 sb2 = base + ((u32)((kt+1) & 1)) * STAGE_B;
            const int ko = (kt + 1) * 64;
            load_stage(sb2, lo, getA(ko), Bp + ko);
            CP_COMMIT();
            CP_WAIT1();
        } else {
            CP_WAIT0();
        }
        __syncthreads();
        mma_chunk(acc, cx, base + ((u32)(kt & 1)) * STAGE_B);
    }

    // epilogue: tanh(acc + bc) -> out
    const int lane = tid & 31;
    const int wm = (tid >> 5) >> 2, wn = (tid >> 5) & 3;
#pragma unroll
    for (int ni = 0; ni < 4; ni++) {
        const int colb = d0 + wn*32 + ni*8 + 2*(lane & 3);
        const float2 bcv = *(const float2*)(bc + colb);
#pragma unroll
        for (int mi = 0; mi < 4; mi++) {
            const int row0 = n0 + wm*64 + mi*16 + (lane >> 2);
            float2 o0, o1;
            o0.x = tanh_acc(acc[mi][ni][0] + bcv.x);
            o0.y = tanh_acc(acc[mi][ni][1] + bcv.y);
            o1.x = tanh_acc(acc[mi][ni][2] + bcv.x);
            o1.y = tanh_acc(acc[mi][ni][3] + bcv.y);
            *(float2*)(out + (size_t)row0 * DD + colb) = o0;
            *(float2*)(out + (size_t)(row0 + 8) * DD + colb) = o1;
        }
    }
}

// =====================================================================
// converters: fp32 -> fp16 (round to nearest)
// =====================================================================
struct __align__(8) hf4 { __half v[4]; };

__device__ __forceinline__ void round4h(const float* __restrict__ src,
                                        __half* __restrict__ dst, int i) {
    float4 v = ((const float4*)src)[i];
    hf4 h;
    h.v[0] = __float2half_rn(v.x); h.v[1] = __float2half_rn(v.y);
    h.v[2] = __float2half_rn(v.z); h.v[3] = __float2half_rn(v.w);
    ((hf4*)dst)[i] = h;
}
__global__ void cvt_x(const float* __restrict__ src) {
    int i = blockIdx.x * blockDim.x + threadIdx.x;
    if (i < NTOK * (DD/4)) round4h(src, g_X16, i);
}
__global__ void cvt_w1(const float* __restrict__ src) {
    int i = blockIdx.x * blockDim.x + threadIdx.x;
    if (i < DD * (DD/4)) round4h(src, g_W1, i);
}
__global__ void cvt_wc(const float* __restrict__ src) {
    int i = blockIdx.x * blockDim.x + threadIdx.x;
    if (i < DD * (K2/4)) round4h(src, g_Wc, i);
}

// =====================================================================
extern "C" void kernel_launch(void* const* d_in, const int* in_sizes, int n_in,
                              void* d_out, int out_size)
{
    const float* x  = (const float*)d_in[0];
    const float* W1 = (const float*)d_in[1];
    const float* b1 = (const float*)d_in[2];
    const float* w2 = (const float*)d_in[3];
    const float* b2 = (const float*)d_in[4];
    const float* Wc = (const float*)d_in[5];
    const float* bc = (const float*)d_in[6];
    float* out = (float*)d_out;

    cudaFuncSetAttribute(gemm_score_mma, cudaFuncAttributeMaxDynamicSharedMemorySize, DYN_B);
    cudaFuncSetAttribute(gemm_out_mma,   cudaFuncAttributeMaxDynamicSharedMemorySize, DYN_B);

    cvt_x <<<(NTOK*(DD/4) + 255)/256, 256>>>(x);
    cvt_w1<<<(DD*(DD/4)   + 255)/256, 256>>>(W1);
    cvt_wc<<<(DD*(K2/4)   + 255)/256, 256>>>(Wc);

    dim3 g1(DD / 128, NTOK / 256);      // (8, 128): e-tiles fast, share A
    gemm_score_mma<<<g1, 512, DYN_B>>>(b1, w2);

    softmax_prep<<<BB, 256>>>(b2);

    dim3 gp(DD / 128, BB, NCHK - 1);
    scan_part<<<gp, 128>>>(x);
    prefP<<<BB, 1024>>>();
    dim3 gf(DD / 128, BB, NCHK);
    scan_final<<<gf, 128>>>(x);

    dim3 g4(DD / 128, NTOK / 256);      // (8, 128): d-tiles fast
    gemm_out_mma<<<g4, 512, DYN_B>>>(bc, out);
}

// round 14
// speedup vs baseline: 1.3259x; 1.0729x over previous
#include <cuda_runtime.h>
#include <cuda_fp16.h>
#include <math.h>

// Problem constants
#define BB   8
#define TT   4096
#define DD   1024
#define NTOK (BB*TT)          // 32768
#define K2   (2*DD)           // 2048
#define NCHK 8
#define CHKT 512

using u32 = unsigned int;
using u64 = unsigned long long;

// ---------------- scratch (static device globals: allowed) ----------------
__device__ float g_spart[8 * NTOK];
__device__ float g_e[NTOK];
__device__ float g_P[BB * NCHK * DD];     // per-chunk partial num sums
__device__ float g_den0[BB * NCHK];       // exclusive prefix of chunk e-sums
__device__ __half g_X16[(size_t)NTOK * DD];  // X fp16
__device__ __half g_C16[(size_t)NTOK * DD];  // ctx fp16
__device__ __half g_W1[(size_t)DD * DD];     // W1 fp16
__device__ __half g_Wc[(size_t)DD * K2];     // Wc fp16

// ---------------- helpers ----------------
__device__ __forceinline__ u32 smem_u32(const void* p) {
    u32 a;
    asm("{ .reg .u64 t; cvta.to.shared.u64 t, %1; cvt.u32.u64 %0, t; }" : "=r"(a) : "l"(p));
    return a;
}
__device__ __forceinline__ void cp16(u32 dst, const void* src) {
    asm volatile("cp.async.cg.shared.global [%0], [%1], 16;" :: "r"(dst), "l"(src));
}
#define CP_COMMIT() asm volatile("cp.async.commit_group;" ::: "memory")
#define CP_WAIT1()  asm volatile("cp.async.wait_group 1;" ::: "memory")
#define CP_WAIT0()  asm volatile("cp.async.wait_group 0;" ::: "memory")

__device__ __forceinline__ void ldsm4(u32* r, u32 addr) {
    asm volatile("ldmatrix.sync.aligned.m8n8.x4.shared.b16 {%0,%1,%2,%3}, [%4];"
                 : "=r"(r[0]), "=r"(r[1]), "=r"(r[2]), "=r"(r[3]) : "r"(addr));
}
__device__ __forceinline__ void hmma(float* c, const u32* a, u32 b0, u32 b1) {
    asm("mma.sync.aligned.m16n8k16.row.col.f32.f16.f16.f32 "
        "{%0,%1,%2,%3}, {%4,%5,%6,%7}, {%8,%9}, {%0,%1,%2,%3};"
        : "+f"(c[0]), "+f"(c[1]), "+f"(c[2]), "+f"(c[3])
        : "r"(a[0]), "r"(a[1]), "r"(a[2]), "r"(a[3]), "r"(b0), "r"(b1));
}
// accurate fast tanh: 1 - 2/(1+e^{2x})
__device__ __forceinline__ float tanh_acc(float x) {
    float e, r;
    asm("ex2.approx.f32 %0, %1;" : "=f"(e) : "f"(x * 2.885390081777927f));
    asm("rcp.approx.f32 %0, %1;" : "=f"(r) : "f"(e + 1.0f));
    return fmaf(-2.0f, r, 1.0f);
}

// ---------------- tile geometry ----------------
// CTA tile 128(M) x 128(N), K-chunk 64. 8 warps (2x4), warp tile 64x32.
// 32KB/stage, 2 stages -> 65KB dyn smem -> 2 CTAs/SM (cross-CTA overlap of
// the per-chunk barrier/wait windows that intra-CTA warps cannot hide).
#define A_TILE   16384                 // 128 x 64 fp16
#define B_TILE   16384                 // 128 x 64 fp16
#define STAGE_B  (A_TILE + B_TILE)     // 32 KB
#define DYN_B    (2*STAGE_B + 1024)

// per-lane fragment addressing constants
struct LaneCtx {
    u32 raoff[4];   // A row offsets per 16-row m tile (warp covers m=64)
    u32 rboff[2];   // B row offsets per 16-row n-pair (warp covers n=32)
    u32 colk[4];    // swizzled column offset per k16
};
__device__ __forceinline__ LaneCtx make_ctx(int tid) {
    LaneCtx cx;
    const int lane = tid & 31;
    const int wm = (tid >> 5) >> 2;        // 0..1
    const int wn = (tid >> 5) & 3;         // 0..3
    const int quad = lane >> 3, r8 = lane & 7;
    const int cb = (quad >> 1) << 4;
    const int rsel = ((quad & 1) << 3) + r8;
    const u32 xsw = (u32)(r8 << 4);
#pragma unroll
    for (int mi = 0; mi < 4; mi++) cx.raoff[mi] = (u32)((wm*64 + mi*16 + rsel) * 128);
#pragma unroll
    for (int p = 0; p < 2; p++)    cx.rboff[p]  = (u32)((wn*32 + p*16 + rsel) * 128);
#pragma unroll
    for (int k = 0; k < 4; k++)    cx.colk[k]   = ((u32)(cb + k*32)) ^ xsw;
    return cx;
}

// precomputed load offsets (global elt offset + swizzled smem offset), 256 thr
struct LoadOff {
    u32 ag[4], as_[4];   // A tile: 4 cp16 per thread (128 rows x 64 cols)
    u32 bg[4], bs_[4];   // B tile: 4 cp16 per thread (128 rows x 64 cols)
};
__device__ __forceinline__ LoadOff make_loff(int tid, int bstride) {
    LoadOff lo;
#pragma unroll
    for (int i = 0; i < 4; i++) {
        int idx = tid + (i << 8);
        int row = idx >> 3, c8 = (idx & 7) << 3;
        lo.ag[i] = (u32)(row * DD + c8);
        lo.bg[i] = (u32)(row * bstride + c8);
        u32 off = (u32)(row * 128 + (c8 << 1));
        u32 sw = off ^ ((off >> 3) & 0x70u);
        lo.as_[i] = sw;
        lo.bs_[i] = sw;
    }
    return lo;
}

__device__ __forceinline__ void load_stage(u32 sb2, const LoadOff& lo,
                                           const __half* pA, const __half* pB) {
#pragma unroll
    for (int i = 0; i < 4; i++)
        cp16(sb2 + lo.as_[i], pA + lo.ag[i]);
#pragma unroll
    for (int i = 0; i < 4; i++)
        cp16(sb2 + A_TILE + lo.bs_[i], pB + lo.bg[i]);
}

// MMA over one resident 64-wide K chunk, warp tile 64x32, single fp16 product.
__device__ __forceinline__ void mma_chunk(float acc[4][4][4], const LaneCtx& cx, u32 stage) {
    const u32 Ab = stage, Bb = stage + A_TILE;
#pragma unroll
    for (int k16 = 0; k16 < 4; k16++) {
        const u32 c = cx.colk[k16];
        u32 b[2][4];
#pragma unroll
        for (int p = 0; p < 2; p++) ldsm4(b[p], Bb + cx.rboff[p] + c);
        u32 a[4][4];
#pragma unroll
        for (int mi = 0; mi < 4; mi++) ldsm4(a[mi], Ab + cx.raoff[mi] + c);
#pragma unroll
        for (int mi = 0; mi < 4; mi++)
#pragma unroll
            for (int ni = 0; ni < 4; ni++) {
                const int p = ni >> 1, s = ni & 1;
                hmma(acc[mi][ni], a[mi], b[p][s], b[p][s+2]);
            }
    }
}

// =====================================================================
// GEMM 1: scores. D[n,e] = X·W1^T; epilogue: spart = sum_e tanh(D+b1)*w2
// grid = (e-tiles=8, n-tiles=256); consecutive blocks share the A tile.
// =====================================================================
__global__ __launch_bounds__(256, 2)
void gemm_score_mma(const float* __restrict__ b1, const float* __restrict__ w2)
{
    extern __shared__ char dyn[];
    __shared__ float red[128][4];
    const int tid = threadIdx.x;
    const int e0 = blockIdx.x * 128;
    const int n0 = blockIdx.y * 128;
    const u32 dynb = smem_u32(dyn);
    const u32 base = (dynb + 1023u) & ~1023u;

    const __half* Ap = g_X16 + (size_t)n0 * DD;
    const __half* Bp = g_W1  + (size_t)e0 * DD;

    const LaneCtx cx = make_ctx(tid);
    const LoadOff lo = make_loff(tid, DD);
    float acc[4][4][4];
#pragma unroll
    for (int i = 0; i < 4; i++)
#pragma unroll
        for (int j = 0; j < 4; j++)
#pragma unroll
            for (int q = 0; q < 4; q++) acc[i][j][q] = 0.f;

    load_stage(base, lo, Ap, Bp);
    CP_COMMIT();

    const int NCH = DD / 64;   // 16
    for (int kt = 0; kt < NCH; kt++) {
        if (kt > 0) __syncthreads();
        if (kt + 1 < NCH) {
            const u32 sb2 = base + ((u32)((kt+1) & 1)) * STAGE_B;
            const int ko = (kt + 1) * 64;
            load_stage(sb2, lo, Ap + ko, Bp + ko);
            CP_COMMIT();
            CP_WAIT1();
        } else {
            CP_WAIT0();
        }
        __syncthreads();
        mma_chunk(acc, cx, base + ((u32)(kt & 1)) * STAGE_B);
    }

    // epilogue: tanh(D+b1)*w2, reduce over the CTA's 128 e-cols
    const int lane = tid & 31;
    const int wm = (tid >> 5) >> 2, wn = (tid >> 5) & 3;
    float b1x[4], b1y[4], w2x[4], w2y[4];
#pragma unroll
    for (int ni = 0; ni < 4; ni++) {
        const int col = e0 + wn*32 + ni*8 + 2*(lane & 3);
        float2 bv = *(const float2*)(b1 + col);
        float2 wv = *(const float2*)(w2 + col);
        b1x[ni] = bv.x; b1y[ni] = bv.y; w2x[ni] = wv.x; w2y[ni] = wv.y;
    }
#pragma unroll
    for (int mi = 0; mi < 4; mi++)
#pragma unroll
        for (int h2 = 0; h2 < 2; h2++) {
            float s = 0.f;
#pragma unroll
            for (int ni = 0; ni < 4; ni++) {
                s += tanh_acc(acc[mi][ni][h2*2+0] + b1x[ni]) * w2x[ni];
                s += tanh_acc(acc[mi][ni][h2*2+1] + b1y[ni]) * w2y[ni];
            }
            s += __shfl_xor_sync(0xffffffffu, s, 1);
            s += __shfl_xor_sync(0xffffffffu, s, 2);
            if ((lane & 3) == 0)
                red[wm*64 + mi*16 + h2*8 + (lane >> 2)][wn] = s;
        }
    __syncthreads();
    if (tid < 128)
        g_spart[(size_t)blockIdx.x * NTOK + n0 + tid] =
            red[tid][0] + red[tid][1] + red[tid][2] + red[tid][3];
}

// =====================================================================
// Kernel 2: per-batch max + e = exp(s + b2 - m); also per-chunk e sums
// =====================================================================
__global__ void softmax_prep(const float* __restrict__ b2)
{
    const int b = blockIdx.x, tid = threadIdx.x;   // 256 threads
    const int lane = tid & 31;
    float vloc[16];
    float mx = -INFINITY;
    const float b2v = b2[0];
#pragma unroll
    for (int i = 0; i < 16; i++) {
        int t = tid + i * 256;
        float s = 0.f;
#pragma unroll
        for (int eb = 0; eb < 8; eb++) s += g_spart[(size_t)eb * NTOK + b * TT + t];
        s += b2v;
        vloc[i] = s;
        mx = fmaxf(mx, s);
    }
    __shared__ float sm[256];
    __shared__ float dsum[NCHK];
    sm[tid] = mx;
    if (tid < NCHK) dsum[tid] = 0.f;
    __syncthreads();
    for (int off = 128; off > 0; off >>= 1) {
        if (tid < off) sm[tid] = fmaxf(sm[tid], sm[tid + off]);
        __syncthreads();
    }
    float m = sm[0];
    float eloc[16];
#pragma unroll
    for (int i = 0; i < 16; i++) {
        int t = tid + i * 256;
        eloc[i] = expf(vloc[i] - m);
        g_e[b * TT + t] = eloc[i];
    }
#pragma unroll
    for (int c = 0; c < NCHK; c++) {
        float v = eloc[2*c] + eloc[2*c+1];
#pragma unroll
        for (int off = 16; off > 0; off >>= 1)
            v += __shfl_xor_sync(0xffffffffu, v, off);
        if (lane == 0) atomicAdd(&dsum[c], v);
    }
    __syncthreads();
    if (tid == 0) {
        float run = 0.f;
#pragma unroll
        for (int c = 0; c < NCHK; c++) { g_den0[b * NCHK + c] = run; run += dsum[c]; }
    }
}

// =====================================================================
// Scan pass A: per-chunk partial sums  P[b,chunk,d] = sum_{t in chunk} e*x
// =====================================================================
__global__ void scan_part(const float* __restrict__ X)
{
    const int b = blockIdx.y, chunk = blockIdx.z;
    const int d = blockIdx.x * 128 + threadIdx.x;
    const float* xb = X + (size_t)b * TT * DD + (size_t)chunk * CHKT * DD + d;
    __shared__ float es[CHKT];
#pragma unroll
    for (int i = 0; i < CHKT/128; i++)
        es[threadIdx.x + i*128] = g_e[b * TT + chunk * CHKT + threadIdx.x + i*128];
    __syncthreads();
    float P = 0.f;
#pragma unroll 8
    for (int tt = 0; tt < CHKT; ++tt)
        P = fmaf(es[tt], xb[(size_t)tt * DD], P);
    g_P[(b * NCHK + chunk) * DD + d] = P;
}

// Exclusive prefix of P over chunks (in place). grid BB, 1024 threads.
__global__ void prefP()
{
    const int b = blockIdx.x, d = threadIdx.x;
    float run = 0.f;
#pragma unroll
    for (int c = 0; c < NCHK; c++) {
        int idx = (b * NCHK + c) * DD + d;
        float t = (c < NCHK-1) ? g_P[idx] : 0.f;
        g_P[idx] = run;
        run += t;
    }
}

// =====================================================================
// Scan pass B: local cumsum + prefix offsets; emits ctx as fp16.
// =====================================================================
__global__ void scan_final(const float* __restrict__ X)
{
    const int b = blockIdx.y, chunk = blockIdx.z;
    const int d = blockIdx.x * 128 + threadIdx.x;
    const size_t rowoff = (size_t)b * TT * DD + (size_t)chunk * CHKT * DD + d;
    const float* xb = X + rowoff;
    __half* cp = g_C16 + rowoff;

    __shared__ float es[CHKT];
#pragma unroll
    for (int i = 0; i < CHKT/128; i++)
        es[threadIdx.x + i*128] = g_e[b * TT + chunk * CHKT + threadIdx.x + i*128];
    __syncthreads();

    float den = g_den0[b * NCHK + chunk];
    float num = g_P[(b * NCHK + chunk) * DD + d];
#pragma unroll 8
    for (int tt = 0; tt < CHKT; ++tt) {
        float ev = es[tt];
        den += ev;
        num = fmaf(ev, xb[(size_t)tt * DD], num);
        float rcp;
        asm("rcp.approx.f32 %0, %1;" : "=f"(rcp) : "f"(den));
        cp[(size_t)tt * DD] = __float2half_rn(num * rcp);
    }
}

// =====================================================================
// GEMM 2: out = tanh([ctx,x]·Wc^T + bc); K split ctx(0:1024)/x(1024:2048)
// grid = (d-tiles=8, n-tiles=256)
// =====================================================================
__global__ __launch_bounds__(256, 2)
void gemm_out_mma(const float* __restrict__ bc, float* __restrict__ out)
{
    extern __shared__ char dyn[];
    const int tid = threadIdx.x;
    const int d0 = blockIdx.x * 128;
    const int n0 = blockIdx.y * 128;
    const u32 dynb = smem_u32(dyn);
    const u32 base = (dynb + 1023u) & ~1023u;

    const __half* Bp = g_Wc + (size_t)d0 * K2;

    const LaneCtx cx = make_ctx(tid);
    const LoadOff lo = make_loff(tid, K2);
    float acc[4][4][4];
#pragma unroll
    for (int i = 0; i < 4; i++)
#pragma unroll
        for (int j = 0; j < 4; j++)
#pragma unroll
            for (int q = 0; q < 4; q++) acc[i][j][q] = 0.f;

    auto getA = [&](int ko) -> const __half* {
        return (ko < DD) ? (g_C16 + (size_t)n0 * DD + ko)
                         : (g_X16 + (size_t)n0 * DD + (ko - DD));
    };

    load_stage(base, lo, getA(0), Bp);
    CP_COMMIT();

    const int NCH = K2 / 64;   // 32
    for (int kt = 0; kt < NCH; kt++) {
        if (kt > 0) __syncthreads();
        if (kt + 1 < NCH) {
            const u32 sb2 = base + ((u32)((kt+1) & 1)) * STAGE_B;
            const int ko = (kt + 1) * 64;
            load_stage(sb2, lo, getA(ko), Bp + ko);
            CP_COMMIT();
            CP_WAIT1();
        } else {
            CP_WAIT0();
        }
        __syncthreads();
        mma_chunk(acc, cx, base + ((u32)(kt & 1)) * STAGE_B);
    }

    // epilogue: tanh(acc + bc) -> out
    const int lane = tid & 31;
    const int wm = (tid >> 5) >> 2, wn = (tid >> 5) & 3;
#pragma unroll
    for (int ni = 0; ni < 4; ni++) {
        const int colb = d0 + wn*32 + ni*8 + 2*(lane & 3);
        const float2 bcv = *(const float2*)(bc + colb);
#pragma unroll
        for (int mi = 0; mi < 4; mi++) {
            const int row0 = n0 + wm*64 + mi*16 + (lane >> 2);
            float2 o0, o1;
            o0.x = tanh_acc(acc[mi][ni][0] + bcv.x);
            o0.y = tanh_acc(acc[mi][ni][1] + bcv.y);
            o1.x = tanh_acc(acc[mi][ni][2] + bcv.x);
            o1.y = tanh_acc(acc[mi][ni][3] + bcv.y);
            *(float2*)(out + (size_t)row0 * DD + colb) = o0;
            *(float2*)(out + (size_t)(row0 + 8) * DD + colb) = o1;
        }
    }
}

// =====================================================================
// converters: fp32 -> fp16 (round to nearest)
// =====================================================================
struct __align__(8) hf4 { __half v[4]; };

__device__ __forceinline__ void round4h(const float* __restrict__ src,
                                        __half* __restrict__ dst, int i) {
    float4 v = ((const float4*)src)[i];
    hf4 h;
    h.v[0] = __float2half_rn(v.x); h.v[1] = __float2half_rn(v.y);
    h.v[2] = __float2half_rn(v.z); h.v[3] = __float2half_rn(v.w);
    ((hf4*)dst)[i] = h;
}
__global__ void cvt_x(const float* __restrict__ src) {
    int i = blockIdx.x * blockDim.x + threadIdx.x;
    if (i < NTOK * (DD/4)) round4h(src, g_X16, i);
}
__global__ void cvt_w1(const float* __restrict__ src) {
    int i = blockIdx.x * blockDim.x + threadIdx.x;
    if (i < DD * (DD/4)) round4h(src, g_W1, i);
}
__global__ void cvt_wc(const float* __restrict__ src) {
    int i = blockIdx.x * blockDim.x + threadIdx.x;
    if (i < DD * (K2/4)) round4h(src, g_Wc, i);
}

// =====================================================================
extern "C" void kernel_launch(void* const* d_in, const int* in_sizes, int n_in,
                              void* d_out, int out_size)
{
    const float* x  = (const float*)d_in[0];
    const float* W1 = (const float*)d_in[1];
    const float* b1 = (const float*)d_in[2];
    const float* w2 = (const float*)d_in[3];
    const float* b2 = (const float*)d_in[4];
    const float* Wc = (const float*)d_in[5];
    const float* bc = (const float*)d_in[6];
    float* out = (float*)d_out;

    cudaFuncSetAttribute(gemm_score_mma, cudaFuncAttributeMaxDynamicSharedMemorySize, DYN_B);
    cudaFuncSetAttribute(gemm_out_mma,   cudaFuncAttributeMaxDynamicSharedMemorySize, DYN_B);

    cvt_x <<<(NTOK*(DD/4) + 255)/256, 256>>>(x);
    cvt_w1<<<(DD*(DD/4)   + 255)/256, 256>>>(W1);
    cvt_wc<<<(DD*(K2/4)   + 255)/256, 256>>>(Wc);

    dim3 g1(DD / 128, NTOK / 128);      // (8, 256): e-tiles fast, share A
    gemm_score_mma<<<g1, 256, DYN_B>>>(b1, w2);

    softmax_prep<<<BB, 256>>>(b2);

    dim3 gp(DD / 128, BB, NCHK - 1);
    scan_part<<<gp, 128>>>(x);
    prefP<<<BB, 1024>>>();
    dim3 gf(DD / 128, BB, NCHK);
    scan_final<<<gf, 128>>>(x);

    dim3 g4(DD / 128, NTOK / 128);      // (8, 256): d-tiles fast
    gemm_out_mma<<<g4, 256, DYN_B>>>(bc, out);
}

// round 15
// speedup vs baseline: 1.3480x; 1.0166x over previous
#include <cuda_runtime.h>
#include <cuda_fp16.h>
#include <math.h>

// Problem constants
#define BB   8
#define TT   4096
#define DD   1024
#define NTOK (BB*TT)          // 32768
#define K2   (2*DD)           // 2048
#define NCHK 8
#define CHKT 512

using u32 = unsigned int;
using u64 = unsigned long long;

// ---------------- scratch (static device globals: allowed) ----------------
__device__ float g_spart[8 * NTOK];
__device__ float g_e[NTOK];
__device__ float g_P[BB * NCHK * DD];     // per-chunk partial num sums
__device__ float g_den0[BB * NCHK];       // exclusive prefix of chunk e-sums
__device__ __half g_X16[(size_t)NTOK * DD];  // X fp16
__device__ __half g_C16[(size_t)NTOK * DD];  // ctx fp16
__device__ __half g_W1[(size_t)DD * DD];     // W1 fp16
__device__ __half g_Wc[(size_t)DD * K2];     // Wc fp16

// ---------------- helpers ----------------
__device__ __forceinline__ u32 smem_u32(const void* p) {
    u32 a;
    asm("{ .reg .u64 t; cvta.to.shared.u64 t, %1; cvt.u32.u64 %0, t; }" : "=r"(a) : "l"(p));
    return a;
}
__device__ __forceinline__ void cp16(u32 dst, const void* src) {
    asm volatile("cp.async.cg.shared.global [%0], [%1], 16;" :: "r"(dst), "l"(src));
}
#define CP_COMMIT() asm volatile("cp.async.commit_group;" ::: "memory")
#define CP_WAIT1()  asm volatile("cp.async.wait_group 1;" ::: "memory")
#define CP_WAIT0()  asm volatile("cp.async.wait_group 0;" ::: "memory")

__device__ __forceinline__ void ldsm4(u32* r, u32 addr) {
    asm volatile("ldmatrix.sync.aligned.m8n8.x4.shared.b16 {%0,%1,%2,%3}, [%4];"
                 : "=r"(r[0]), "=r"(r[1]), "=r"(r[2]), "=r"(r[3]) : "r"(addr));
}
__device__ __forceinline__ void hmma(float* c, const u32* a, u32 b0, u32 b1) {
    asm("mma.sync.aligned.m16n8k16.row.col.f32.f16.f16.f32 "
        "{%0,%1,%2,%3}, {%4,%5,%6,%7}, {%8,%9}, {%0,%1,%2,%3};"
        : "+f"(c[0]), "+f"(c[1]), "+f"(c[2]), "+f"(c[3])
        : "r"(a[0]), "r"(a[1]), "r"(a[2]), "r"(a[3]), "r"(b0), "r"(b1));
}
// accurate fast tanh: 1 - 2/(1+e^{2x})
__device__ __forceinline__ float tanh_acc(float x) {
    float e, r;
    asm("ex2.approx.f32 %0, %1;" : "=f"(e) : "f"(x * 2.885390081777927f));
    asm("rcp.approx.f32 %0, %1;" : "=f"(r) : "f"(e + 1.0f));
    return fmaf(-2.0f, r, 1.0f);
}

// ---------------- tile geometry ----------------
// CTA tile 128(M) x 128(N), K-chunk 64. 8 warps (2x4), warp tile 64x32.
// 3-stage ring (32KB each) -> ONE barrier per chunk + 2-chunk prefetch.
// ~97KB dyn smem, 128 regs -> 2 CTAs/SM (cross-CTA edge overlap).
#define A_TILE   16384                 // 128 x 64 fp16
#define B_TILE   16384                 // 128 x 64 fp16
#define STAGE_B  (A_TILE + B_TILE)     // 32 KB
#define NSTAGE   3
#define DYN_B    (NSTAGE*STAGE_B + 1024)

// per-lane fragment addressing constants
struct LaneCtx {
    u32 raoff[4];   // A row offsets per 16-row m tile (warp covers m=64)
    u32 rboff[2];   // B row offsets per 16-row n-pair (warp covers n=32)
    u32 colk[4];    // swizzled column offset per k16
};
__device__ __forceinline__ LaneCtx make_ctx(int tid) {
    LaneCtx cx;
    const int lane = tid & 31;
    const int wm = (tid >> 5) >> 2;        // 0..1
    const int wn = (tid >> 5) & 3;         // 0..3
    const int quad = lane >> 3, r8 = lane & 7;
    const int cb = (quad >> 1) << 4;
    const int rsel = ((quad & 1) << 3) + r8;
    const u32 xsw = (u32)(r8 << 4);
#pragma unroll
    for (int mi = 0; mi < 4; mi++) cx.raoff[mi] = (u32)((wm*64 + mi*16 + rsel) * 128);
#pragma unroll
    for (int p = 0; p < 2; p++)    cx.rboff[p]  = (u32)((wn*32 + p*16 + rsel) * 128);
#pragma unroll
    for (int k = 0; k < 4; k++)    cx.colk[k]   = ((u32)(cb + k*32)) ^ xsw;
    return cx;
}

// precomputed load offsets (global elt offset + swizzled smem offset), 256 thr
struct LoadOff {
    u32 ag[4], as_[4];   // A tile: 4 cp16 per thread (128 rows x 64 cols)
    u32 bg[4], bs_[4];   // B tile: 4 cp16 per thread (128 rows x 64 cols)
};
__device__ __forceinline__ LoadOff make_loff(int tid, int bstride) {
    LoadOff lo;
#pragma unroll
    for (int i = 0; i < 4; i++) {
        int idx = tid + (i << 8);
        int row = idx >> 3, c8 = (idx & 7) << 3;
        lo.ag[i] = (u32)(row * DD + c8);
        lo.bg[i] = (u32)(row * bstride + c8);
        u32 off = (u32)(row * 128 + (c8 << 1));
        u32 sw = off ^ ((off >> 3) & 0x70u);
        lo.as_[i] = sw;
        lo.bs_[i] = sw;
    }
    return lo;
}

__device__ __forceinline__ void load_stage(u32 sb2, const LoadOff& lo,
                                           const __half* pA, const __half* pB) {
#pragma unroll
    for (int i = 0; i < 4; i++)
        cp16(sb2 + lo.as_[i], pA + lo.ag[i]);
#pragma unroll
    for (int i = 0; i < 4; i++)
        cp16(sb2 + A_TILE + lo.bs_[i], pB + lo.bg[i]);
}

// MMA over one resident 64-wide K chunk, warp tile 64x32, single fp16 product.
__device__ __forceinline__ void mma_chunk(float acc[4][4][4], const LaneCtx& cx, u32 stage) {
    const u32 Ab = stage, Bb = stage + A_TILE;
#pragma unroll
    for (int k16 = 0; k16 < 4; k16++) {
        const u32 c = cx.colk[k16];
        u32 b[2][4];
#pragma unroll
        for (int p = 0; p < 2; p++) ldsm4(b[p], Bb + cx.rboff[p] + c);
        u32 a[4][4];
#pragma unroll
        for (int mi = 0; mi < 4; mi++) ldsm4(a[mi], Ab + cx.raoff[mi] + c);
#pragma unroll
        for (int mi = 0; mi < 4; mi++)
#pragma unroll
            for (int ni = 0; ni < 4; ni++) {
                const int p = ni >> 1, s = ni & 1;
                hmma(acc[mi][ni], a[mi], b[p][s], b[p][s+2]);
            }
    }
}

// 3-stage mainloop skeleton (shared by both GEMMs):
//   prologue: load s0(k0), load s1(k1)
//   iter kt:  CP_WAIT -> sync -> issue load((kt+2)%3) -> mma(kt%3)
// The single sync both publishes stage kt AND proves all warps finished
// mma(kt-1), making the overwrite of stage (kt+2)%3 == (kt-1)%3 safe.

// =====================================================================
// GEMM 1: scores. D[n,e] = X·W1^T; epilogue: spart = sum_e tanh(D+b1)*w2
// grid = (e-tiles=8, n-tiles=256); consecutive blocks share the A tile.
// =====================================================================
__global__ __launch_bounds__(256, 2)
void gemm_score_mma(const float* __restrict__ b1, const float* __restrict__ w2)
{
    extern __shared__ char dyn[];
    __shared__ float red[128][4];
    const int tid = threadIdx.x;
    const int e0 = blockIdx.x * 128;
    const int n0 = blockIdx.y * 128;
    const u32 dynb = smem_u32(dyn);
    const u32 base = (dynb + 1023u) & ~1023u;

    const __half* Ap = g_X16 + (size_t)n0 * DD;
    const __half* Bp = g_W1  + (size_t)e0 * DD;

    const LaneCtx cx = make_ctx(tid);
    const LoadOff lo = make_loff(tid, DD);
    float acc[4][4][4];
#pragma unroll
    for (int i = 0; i < 4; i++)
#pragma unroll
        for (int j = 0; j < 4; j++)
#pragma unroll
            for (int q = 0; q < 4; q++) acc[i][j][q] = 0.f;

    load_stage(base,           lo, Ap,      Bp);      CP_COMMIT();
    load_stage(base + STAGE_B, lo, Ap + 64, Bp + 64); CP_COMMIT();

    const int NCH = DD / 64;   // 16
    int st = 0;                 // stage index of chunk kt
    for (int kt = 0; kt < NCH; kt++) {
        if (kt + 1 < NCH) { CP_WAIT1(); } else { CP_WAIT0(); }
        __syncthreads();
        if (kt + 2 < NCH) {
            int s2 = st + 2; if (s2 >= NSTAGE) s2 -= NSTAGE;
            const int ko = (kt + 2) * 64;
            load_stage(base + (u32)s2 * STAGE_B, lo, Ap + ko, Bp + ko);
            CP_COMMIT();
        }
        mma_chunk(acc, cx, base + (u32)st * STAGE_B);
        if (++st == NSTAGE) st = 0;
    }

    // epilogue: tanh(D+b1)*w2, reduce over the CTA's 128 e-cols
    const int lane = tid & 31;
    const int wm = (tid >> 5) >> 2, wn = (tid >> 5) & 3;
    float b1x[4], b1y[4], w2x[4], w2y[4];
#pragma unroll
    for (int ni = 0; ni < 4; ni++) {
        const int col = e0 + wn*32 + ni*8 + 2*(lane & 3);
        float2 bv = *(const float2*)(b1 + col);
        float2 wv = *(const float2*)(w2 + col);
        b1x[ni] = bv.x; b1y[ni] = bv.y; w2x[ni] = wv.x; w2y[ni] = wv.y;
    }
#pragma unroll
    for (int mi = 0; mi < 4; mi++)
#pragma unroll
        for (int h2 = 0; h2 < 2; h2++) {
            float s = 0.f;
#pragma unroll
            for (int ni = 0; ni < 4; ni++) {
                s += tanh_acc(acc[mi][ni][h2*2+0] + b1x[ni]) * w2x[ni];
                s += tanh_acc(acc[mi][ni][h2*2+1] + b1y[ni]) * w2y[ni];
            }
            s += __shfl_xor_sync(0xffffffffu, s, 1);
            s += __shfl_xor_sync(0xffffffffu, s, 2);
            if ((lane & 3) == 0)
                red[wm*64 + mi*16 + h2*8 + (lane >> 2)][wn] = s;
        }
    __syncthreads();
    if (tid < 128)
        g_spart[(size_t)blockIdx.x * NTOK + n0 + tid] =
            red[tid][0] + red[tid][1] + red[tid][2] + red[tid][3];
}

// =====================================================================
// Kernel 2: per-batch max + e = exp(s + b2 - m); also per-chunk e sums
// =====================================================================
__global__ void softmax_prep(const float* __restrict__ b2)
{
    const int b = blockIdx.x, tid = threadIdx.x;   // 256 threads
    const int lane = tid & 31;
    float vloc[16];
    float mx = -INFINITY;
    const float b2v = b2[0];
#pragma unroll
    for (int i = 0; i < 16; i++) {
        int t = tid + i * 256;
        float s = 0.f;
#pragma unroll
        for (int eb = 0; eb < 8; eb++) s += g_spart[(size_t)eb * NTOK + b * TT + t];
        s += b2v;
        vloc[i] = s;
        mx = fmaxf(mx, s);
    }
    __shared__ float sm[256];
    __shared__ float dsum[NCHK];
    sm[tid] = mx;
    if (tid < NCHK) dsum[tid] = 0.f;
    __syncthreads();
    for (int off = 128; off > 0; off >>= 1) {
        if (tid < off) sm[tid] = fmaxf(sm[tid], sm[tid + off]);
        __syncthreads();
    }
    float m = sm[0];
    float eloc[16];
#pragma unroll
    for (int i = 0; i < 16; i++) {
        int t = tid + i * 256;
        eloc[i] = expf(vloc[i] - m);
        g_e[b * TT + t] = eloc[i];
    }
#pragma unroll
    for (int c = 0; c < NCHK; c++) {
        float v = eloc[2*c] + eloc[2*c+1];
#pragma unroll
        for (int off = 16; off > 0; off >>= 1)
            v += __shfl_xor_sync(0xffffffffu, v, off);
        if (lane == 0) atomicAdd(&dsum[c], v);
    }
    __syncthreads();
    if (tid == 0) {
        float run = 0.f;
#pragma unroll
        for (int c = 0; c < NCHK; c++) { g_den0[b * NCHK + c] = run; run += dsum[c]; }
    }
}

// =====================================================================
// Scan pass A: per-chunk partial sums  P[b,chunk,d] = sum_{t in chunk} e*x
// =====================================================================
__global__ void scan_part(const float* __restrict__ X)
{
    const int b = blockIdx.y, chunk = blockIdx.z;
    const int d = blockIdx.x * 128 + threadIdx.x;
    const float* xb = X + (size_t)b * TT * DD + (size_t)chunk * CHKT * DD + d;
    __shared__ float es[CHKT];
#pragma unroll
    for (int i = 0; i < CHKT/128; i++)
        es[threadIdx.x + i*128] = g_e[b * TT + chunk * CHKT + threadIdx.x + i*128];
    __syncthreads();
    float P = 0.f;
#pragma unroll 8
    for (int tt = 0; tt < CHKT; ++tt)
        P = fmaf(es[tt], xb[(size_t)tt * DD], P);
    g_P[(b * NCHK + chunk) * DD + d] = P;
}

// Exclusive prefix of P over chunks (in place). grid BB, 1024 threads.
__global__ void prefP()
{
    const int b = blockIdx.x, d = threadIdx.x;
    float run = 0.f;
#pragma unroll
    for (int c = 0; c < NCHK; c++) {
        int idx = (b * NCHK + c) * DD + d;
        float t = (c < NCHK-1) ? g_P[idx] : 0.f;
        g_P[idx] = run;
        run += t;
    }
}

// =====================================================================
// Scan pass B: local cumsum + prefix offsets; emits ctx as fp16.
// =====================================================================
__global__ void scan_final(const float* __restrict__ X)
{
    const int b = blockIdx.y, chunk = blockIdx.z;
    const int d = blockIdx.x * 128 + threadIdx.x;
    const size_t rowoff = (size_t)b * TT * DD + (size_t)chunk * CHKT * DD + d;
    const float* xb = X + rowoff;
    __half* cp = g_C16 + rowoff;

    __shared__ float es[CHKT];
#pragma unroll
    for (int i = 0; i < CHKT/128; i++)
        es[threadIdx.x + i*128] = g_e[b * TT + chunk * CHKT + threadIdx.x + i*128];
    __syncthreads();

    float den = g_den0[b * NCHK + chunk];
    float num = g_P[(b * NCHK + chunk) * DD + d];
#pragma unroll 8
    for (int tt = 0; tt < CHKT; ++tt) {
        float ev = es[tt];
        den += ev;
        num = fmaf(ev, xb[(size_t)tt * DD], num);
        float rcp;
        asm("rcp.approx.f32 %0, %1;" : "=f"(rcp) : "f"(den));
        cp[(size_t)tt * DD] = __float2half_rn(num * rcp);
    }
}

// =====================================================================
// GEMM 2: out = tanh([ctx,x]·Wc^T + bc); K split ctx(0:1024)/x(1024:2048)
// grid = (d-tiles=8, n-tiles=256)
// =====================================================================
__global__ __launch_bounds__(256, 2)
void gemm_out_mma(const float* __restrict__ bc, float* __restrict__ out)
{
    extern __shared__ char dyn[];
    const int tid = threadIdx.x;
    const int d0 = blockIdx.x * 128;
    const int n0 = blockIdx.y * 128;
    const u32 dynb = smem_u32(dyn);
    const u32 base = (dynb + 1023u) & ~1023u;

    const __half* Bp = g_Wc + (size_t)d0 * K2;

    const LaneCtx cx = make_ctx(tid);
    const LoadOff lo = make_loff(tid, K2);
    float acc[4][4][4];
#pragma unroll
    for (int i = 0; i < 4; i++)
#pragma unroll
        for (int j = 0; j < 4; j++)
#pragma unroll
            for (int q = 0; q < 4; q++) acc[i][j][q] = 0.f;

    auto getA = [&](int ko) -> const __half* {
        return (ko < DD) ? (g_C16 + (size_t)n0 * DD + ko)
                         : (g_X16 + (size_t)n0 * DD + (ko - DD));
    };

    load_stage(base,           lo, getA(0),  Bp);      CP_COMMIT();
    load_stage(base + STAGE_B, lo, getA(64), Bp + 64); CP_COMMIT();

    const int NCH = K2 / 64;   // 32
    int st = 0;
    for (int kt = 0; kt < NCH; kt++) {
        if (kt + 1 < NCH) { CP_WAIT1(); } else { CP_WAIT0(); }
        __syncthreads();
        if (kt + 2 < NCH) {
            int s2 = st + 2; if (s2 >= NSTAGE) s2 -= NSTAGE;
            const int ko = (kt + 2) * 64;
            load_stage(base + (u32)s2 * STAGE_B, lo, getA(ko), Bp + ko);
            CP_COMMIT();
        }
        mma_chunk(acc, cx, base + (u32)st * STAGE_B);
        if (++st == NSTAGE) st = 0;
    }

    // epilogue: tanh(acc + bc) -> out
    const int lane = tid & 31;
    const int wm = (tid >> 5) >> 2, wn = (tid >> 5) & 3;
#pragma unroll
    for (int ni = 0; ni < 4; ni++) {
        const int colb = d0 + wn*32 + ni*8 + 2*(lane & 3);
        const float2 bcv = *(const float2*)(bc + colb);
#pragma unroll
        for (int mi = 0; mi < 4; mi++) {
            const int row0 = n0 + wm*64 + mi*16 + (lane >> 2);
            float2 o0, o1;
            o0.x = tanh_acc(acc[mi][ni][0] + bcv.x);
            o0.y = tanh_acc(acc[mi][ni][1] + bcv.y);
            o1.x = tanh_acc(acc[mi][ni][2] + bcv.x);
            o1.y = tanh_acc(acc[mi][ni][3] + bcv.y);
            *(float2*)(out + (size_t)row0 * DD + colb) = o0;
            *(float2*)(out + (size_t)(row0 + 8) * DD + colb) = o1;
        }
    }
}

// =====================================================================
// converters: fp32 -> fp16 (round to nearest)
// =====================================================================
struct __align__(8) hf4 { __half v[4]; };

__device__ __forceinline__ void round4h(const float* __restrict__ src,
                                        __half* __restrict__ dst, int i) {
    float4 v = ((const float4*)src)[i];
    hf4 h;
    h.v[0] = __float2half_rn(v.x); h.v[1] = __float2half_rn(v.y);
    h.v[2] = __float2half_rn(v.z); h.v[3] = __float2half_rn(v.w);
    ((hf4*)dst)[i] = h;
}
__global__ void cvt_x(const float* __restrict__ src) {
    int i = blockIdx.x * blockDim.x + threadIdx.x;
    if (i < NTOK * (DD/4)) round4h(src, g_X16, i);
}
__global__ void cvt_w1(const float* __restrict__ src) {
    int i = blockIdx.x * blockDim.x + threadIdx.x;
    if (i < DD * (DD/4)) round4h(src, g_W1, i);
}
__global__ void cvt_wc(const float* __restrict__ src) {
    int i = blockIdx.x * blockDim.x + threadIdx.x;
    if (i < DD * (K2/4)) round4h(src, g_Wc, i);
}

// =====================================================================
extern "C" void kernel_launch(void* const* d_in, const int* in_sizes, int n_in,
                              void* d_out, int out_size)
{
    const float* x  = (const float*)d_in[0];
    const float* W1 = (const float*)d_in[1];
    const float* b1 = (const float*)d_in[2];
    const float* w2 = (const float*)d_in[3];
    const float* b2 = (const float*)d_in[4];
    const float* Wc = (const float*)d_in[5];
    const float* bc = (const float*)d_in[6];
    float* out = (float*)d_out;

    cudaFuncSetAttribute(gemm_score_mma, cudaFuncAttributeMaxDynamicSharedMemorySize, DYN_B);
    cudaFuncSetAttribute(gemm_out_mma,   cudaFuncAttributeMaxDynamicSharedMemorySize, DYN_B);

    cvt_x <<<(NTOK*(DD/4) + 255)/256, 256>>>(x);
    cvt_w1<<<(DD*(DD/4)   + 255)/256, 256>>>(W1);
    cvt_wc<<<(DD*(K2/4)   + 255)/256, 256>>>(Wc);

    dim3 g1(DD / 128, NTOK / 128);      // (8, 256): e-tiles fast, share A
    gemm_score_mma<<<g1, 256, DYN_B>>>(b1, w2);

    softmax_prep<<<BB, 256>>>(b2);

    dim3 gp(DD / 128, BB, NCHK - 1);
    scan_part<<<gp, 128>>>(x);
    prefP<<<BB, 1024>>>();
    dim3 gf(DD / 128, BB, NCHK);
    scan_final<<<gf, 128>>>(x);

    dim3 g4(DD / 128, NTOK / 128);      // (8, 256): d-tiles fast
    gemm_out_mma<<<g4, 256, DYN_B>>>(bc, out);
}

// round 16
// speedup vs baseline: 1.3600x; 1.0089x over previous
#include <cuda_runtime.h>
#include <cuda_fp16.h>
#include <math.h>

// Problem constants
#define BB   8
#define TT   4096
#define DD   1024
#define NTOK (BB*TT)          // 32768
#define K2   (2*DD)           // 2048
#define NCHK 8
#define CHKT 512
#define NEB  16               // e-tiles (64 cols each) for score partials

using u32 = unsigned int;
using u64 = unsigned long long;

// ---------------- scratch (static device globals: allowed) ----------------
__device__ float g_spart[NEB * NTOK];
__device__ float g_e[NTOK];
__device__ float g_P[BB * NCHK * DD];     // per-chunk partial num sums
__device__ float g_den0[BB * NCHK];       // exclusive prefix of chunk e-sums
__device__ __half g_X16[(size_t)NTOK * DD];  // X fp16
__device__ __half g_C16[(size_t)NTOK * DD];  // ctx fp16
__device__ __half g_W1[(size_t)DD * DD];     // W1 fp16
__device__ __half g_Wc[(size_t)DD * K2];     // Wc fp16

// ---------------- helpers ----------------
__device__ __forceinline__ u32 smem_u32(const void* p) {
    u32 a;
    asm("{ .reg .u64 t; cvta.to.shared.u64 t, %1; cvt.u32.u64 %0, t; }" : "=r"(a) : "l"(p));
    return a;
}
__device__ __forceinline__ void cp16(u32 dst, const void* src) {
    asm volatile("cp.async.cg.shared.global [%0], [%1], 16;" :: "r"(dst), "l"(src));
}
#define CP_COMMIT() asm volatile("cp.async.commit_group;" ::: "memory")
#define CP_WAIT1()  asm volatile("cp.async.wait_group 1;" ::: "memory")
#define CP_WAIT0()  asm volatile("cp.async.wait_group 0;" ::: "memory")

__device__ __forceinline__ void ldsm4(u32* r, u32 addr) {
    asm volatile("ldmatrix.sync.aligned.m8n8.x4.shared.b16 {%0,%1,%2,%3}, [%4];"
                 : "=r"(r[0]), "=r"(r[1]), "=r"(r[2]), "=r"(r[3]) : "r"(addr));
}
__device__ __forceinline__ void hmma(float* c, const u32* a, u32 b0, u32 b1) {
    asm("mma.sync.aligned.m16n8k16.row.col.f32.f16.f16.f32 "
        "{%0,%1,%2,%3}, {%4,%5,%6,%7}, {%8,%9}, {%0,%1,%2,%3};"
        : "+f"(c[0]), "+f"(c[1]), "+f"(c[2]), "+f"(c[3])
        : "r"(a[0]), "r"(a[1]), "r"(a[2]), "r"(a[3]), "r"(b0), "r"(b1));
}
// accurate fast tanh: 1 - 2/(1+e^{2x})
__device__ __forceinline__ float tanh_acc(float x) {
    float e, r;
    asm("ex2.approx.f32 %0, %1;" : "=f"(e) : "f"(x * 2.885390081777927f));
    asm("rcp.approx.f32 %0, %1;" : "=f"(r) : "f"(e + 1.0f));
    return fmaf(-2.0f, r, 1.0f);
}

// ---------------- tile geometry ----------------
// CTA tile 128(M) x 64(N), K-chunk 64. 4 warps (2x2), warp tile 64x32.
// 24KB/stage, 2 stages -> ~50KB dyn smem, <=170 regs -> 3 CTAs/SM.
// Each SMSP hosts 3 warps from 3 INDEPENDENT CTAs (no shared barrier):
// the ldsm/load bursts of one CTA overlap the HMMA bursts of the others.
#define A_TILE   16384                 // 128 x 64 fp16
#define B_TILE   8192                  //  64 x 64 fp16
#define STAGE_B  (A_TILE + B_TILE)     // 24 KB
#define DYN_B    (2*STAGE_B + 1024)    // ~50 KB

// per-lane fragment addressing constants
struct LaneCtx {
    u32 raoff[4];   // A row offsets per 16-row m tile (warp covers m=64)
    u32 rboff[2];   // B row offsets per 16-row n-pair (warp covers n=32)
    u32 colk[4];    // swizzled column offset per k16
};
__device__ __forceinline__ LaneCtx make_ctx(int tid) {
    LaneCtx cx;
    const int lane = tid & 31;
    const int wm = (tid >> 5) >> 1;        // 0..1
    const int wn = (tid >> 5) & 1;         // 0..1
    const int quad = lane >> 3, r8 = lane & 7;
    const int cb = (quad >> 1) << 4;
    const int rsel = ((quad & 1) << 3) + r8;
    const u32 xsw = (u32)(r8 << 4);
#pragma unroll
    for (int mi = 0; mi < 4; mi++) cx.raoff[mi] = (u32)((wm*64 + mi*16 + rsel) * 128);
#pragma unroll
    for (int p = 0; p < 2; p++)    cx.rboff[p]  = (u32)((wn*32 + p*16 + rsel) * 128);
#pragma unroll
    for (int k = 0; k < 4; k++)    cx.colk[k]   = ((u32)(cb + k*32)) ^ xsw;
    return cx;
}

// load offsets: base + linear stride (SW128 xor is invariant under row+=16,
// so smem offsets advance by exactly 16*128 = 2048 bytes per step).
struct LoadOff {
    u32 ag0, as0;   // A base (elt offset / swizzled byte offset)
    u32 bg0, bs0;   // B base
};
__device__ __forceinline__ LoadOff make_loff(int tid, int bstride) {
    LoadOff lo;
    const int row = tid >> 3, c8 = (tid & 7) << 3;
    lo.ag0 = (u32)(row * DD + c8);
    lo.bg0 = (u32)(row * bstride + c8);
    u32 off = (u32)(row * 128 + (c8 << 1));
    u32 sw = off ^ ((off >> 3) & 0x70u);
    lo.as0 = sw;
    lo.bs0 = sw;
    return lo;
}

// A: 128 rows (8 steps of 16), B: 64 rows (4 steps of 16); 128 threads
__device__ __forceinline__ void load_stage(u32 sb2, const LoadOff& lo, int bstride,
                                           const __half* pA, const __half* pB) {
#pragma unroll
    for (int i = 0; i < 8; i++)
        cp16(sb2 + lo.as0 + (u32)(i*2048), pA + lo.ag0 + i*16*DD);
#pragma unroll
    for (int i = 0; i < 4; i++)
        cp16(sb2 + A_TILE + lo.bs0 + (u32)(i*2048), pB + lo.bg0 + i*16*bstride);
}

// MMA over one resident 64-wide K chunk, warp tile 64x32, single fp16 product.
__device__ __forceinline__ void mma_chunk(float acc[4][4][4], const LaneCtx& cx, u32 stage) {
    const u32 Ab = stage, Bb = stage + A_TILE;
#pragma unroll
    for (int k16 = 0; k16 < 4; k16++) {
        const u32 c = cx.colk[k16];
        u32 b[2][4];
#pragma unroll
        for (int p = 0; p < 2; p++) ldsm4(b[p], Bb + cx.rboff[p] + c);
        u32 a[4][4];
#pragma unroll
        for (int mi = 0; mi < 4; mi++) ldsm4(a[mi], Ab + cx.raoff[mi] + c);
#pragma unroll
        for (int mi = 0; mi < 4; mi++)
#pragma unroll
            for (int ni = 0; ni < 4; ni++) {
                const int p = ni >> 1, s = ni & 1;
                hmma(acc[mi][ni], a[mi], b[p][s], b[p][s+2]);
            }
    }
}

// =====================================================================
// GEMM 1: scores. D[n,e] = X·W1^T; epilogue: spart = sum_e tanh(D+b1)*w2
// grid = (e-tiles=16, n-tiles=256); consecutive blocks share the A tile.
// =====================================================================
__global__ __launch_bounds__(128, 3)
void gemm_score_mma(const float* __restrict__ b1, const float* __restrict__ w2)
{
    extern __shared__ char dyn[];
    __shared__ float red[128][2];
    const int tid = threadIdx.x;
    const int e0 = blockIdx.x * 64;
    const int n0 = blockIdx.y * 128;
    const u32 dynb = smem_u32(dyn);
    const u32 base = (dynb + 1023u) & ~1023u;

    const __half* Ap = g_X16 + (size_t)n0 * DD;
    const __half* Bp = g_W1  + (size_t)e0 * DD;

    const LaneCtx cx = make_ctx(tid);
    const LoadOff lo = make_loff(tid, DD);
    float acc[4][4][4];
#pragma unroll
    for (int i = 0; i < 4; i++)
#pragma unroll
        for (int j = 0; j < 4; j++)
#pragma unroll
            for (int q = 0; q < 4; q++) acc[i][j][q] = 0.f;

    load_stage(base, lo, DD, Ap, Bp);
    CP_COMMIT();

    const int NCH = DD / 64;   // 16
    for (int kt = 0; kt < NCH; kt++) {
        if (kt > 0) __syncthreads();
        if (kt + 1 < NCH) {
            const u32 sb2 = base + ((u32)((kt+1) & 1)) * STAGE_B;
            const int ko = (kt + 1) * 64;
            load_stage(sb2, lo, DD, Ap + ko, Bp + ko);
            CP_COMMIT();
            CP_WAIT1();
        } else {
            CP_WAIT0();
        }
        __syncthreads();
        mma_chunk(acc, cx, base + ((u32)(kt & 1)) * STAGE_B);
    }

    // epilogue: tanh(D+b1)*w2, reduce over the CTA's 64 e-cols
    const int lane = tid & 31;
    const int wm = (tid >> 5) >> 1, wn = (tid >> 5) & 1;
    float b1x[4], b1y[4], w2x[4], w2y[4];
#pragma unroll
    for (int ni = 0; ni < 4; ni++) {
        const int col = e0 + wn*32 + ni*8 + 2*(lane & 3);
        float2 bv = *(const float2*)(b1 + col);
        float2 wv = *(const float2*)(w2 + col);
        b1x[ni] = bv.x; b1y[ni] = bv.y; w2x[ni] = wv.x; w2y[ni] = wv.y;
    }
#pragma unroll
    for (int mi = 0; mi < 4; mi++)
#pragma unroll
        for (int h2 = 0; h2 < 2; h2++) {
            float s = 0.f;
#pragma unroll
            for (int ni = 0; ni < 4; ni++) {
                s += tanh_acc(acc[mi][ni][h2*2+0] + b1x[ni]) * w2x[ni];
                s += tanh_acc(acc[mi][ni][h2*2+1] + b1y[ni]) * w2y[ni];
            }
            s += __shfl_xor_sync(0xffffffffu, s, 1);
            s += __shfl_xor_sync(0xffffffffu, s, 2);
            if ((lane & 3) == 0)
                red[wm*64 + mi*16 + h2*8 + (lane >> 2)][wn] = s;
        }
    __syncthreads();
    g_spart[(size_t)blockIdx.x * NTOK + n0 + tid] = red[tid][0] + red[tid][1];
}

// =====================================================================
// Kernel 2: per-batch max + e = exp(s + b2 - m); also per-chunk e sums
// =====================================================================
__global__ void softmax_prep(const float* __restrict__ b2)
{
    const int b = blockIdx.x, tid = threadIdx.x;   // 256 threads
    const int lane = tid & 31;
    float vloc[16];
    float mx = -INFINITY;
    const float b2v = b2[0];
#pragma unroll
    for (int i = 0; i < 16; i++) {
        int t = tid + i * 256;
        float s = 0.f;
#pragma unroll
        for (int eb = 0; eb < NEB; eb++) s += g_spart[(size_t)eb * NTOK + b * TT + t];
        s += b2v;
        vloc[i] = s;
        mx = fmaxf(mx, s);
    }
    __shared__ float sm[256];
    __shared__ float dsum[NCHK];
    sm[tid] = mx;
    if (tid < NCHK) dsum[tid] = 0.f;
    __syncthreads();
    for (int off = 128; off > 0; off >>= 1) {
        if (tid < off) sm[tid] = fmaxf(sm[tid], sm[tid + off]);
        __syncthreads();
    }
    float m = sm[0];
    float eloc[16];
#pragma unroll
    for (int i = 0; i < 16; i++) {
        int t = tid + i * 256;
        eloc[i] = expf(vloc[i] - m);
        g_e[b * TT + t] = eloc[i];
    }
#pragma unroll
    for (int c = 0; c < NCHK; c++) {
        float v = eloc[2*c] + eloc[2*c+1];
#pragma unroll
        for (int off = 16; off > 0; off >>= 1)
            v += __shfl_xor_sync(0xffffffffu, v, off);
        if (lane == 0) atomicAdd(&dsum[c], v);
    }
    __syncthreads();
    if (tid == 0) {
        float run = 0.f;
#pragma unroll
        for (int c = 0; c < NCHK; c++) { g_den0[b * NCHK + c] = run; run += dsum[c]; }
    }
}

// =====================================================================
// Scan pass A: per-chunk partial sums  P[b,chunk,d] = sum_{t in chunk} e*x
// =====================================================================
__global__ void scan_part(const float* __restrict__ X)
{
    const int b = blockIdx.y, chunk = blockIdx.z;
    const int d = blockIdx.x * 128 + threadIdx.x;
    const float* xb = X + (size_t)b * TT * DD + (size_t)chunk * CHKT * DD + d;
    __shared__ float es[CHKT];
#pragma unroll
    for (int i = 0; i < CHKT/128; i++)
        es[threadIdx.x + i*128] = g_e[b * TT + chunk * CHKT + threadIdx.x + i*128];
    __syncthreads();
    float P = 0.f;
#pragma unroll 8
    for (int tt = 0; tt < CHKT; ++tt)
        P = fmaf(es[tt], xb[(size_t)tt * DD], P);
    g_P[(b * NCHK + chunk) * DD + d] = P;
}

// Exclusive prefix of P over chunks (in place). grid BB, 1024 threads.
__global__ void prefP()
{
    const int b = blockIdx.x, d = threadIdx.x;
    float run = 0.f;
#pragma unroll
    for (int c = 0; c < NCHK; c++) {
        int idx = (b * NCHK + c) * DD + d;
        float t = (c < NCHK-1) ? g_P[idx] : 0.f;
        g_P[idx] = run;
        run += t;
    }
}

// =====================================================================
// Scan pass B: local cumsum + prefix offsets; emits ctx as fp16.
// =====================================================================
__global__ void scan_final(const float* __restrict__ X)
{
    const int b = blockIdx.y, chunk = blockIdx.z;
    const int d = blockIdx.x * 128 + threadIdx.x;
    const size_t rowoff = (size_t)b * TT * DD + (size_t)chunk * CHKT * DD + d;
    const float* xb = X + rowoff;
    __half* cp = g_C16 + rowoff;

    __shared__ float es[CHKT];
#pragma unroll
    for (int i = 0; i < CHKT/128; i++)
        es[threadIdx.x + i*128] = g_e[b * TT + chunk * CHKT + threadIdx.x + i*128];
    __syncthreads();

    float den = g_den0[b * NCHK + chunk];
    float num = g_P[(b * NCHK + chunk) * DD + d];
#pragma unroll 8
    for (int tt = 0; tt < CHKT; ++tt) {
        float ev = es[tt];
        den += ev;
        num = fmaf(ev, xb[(size_t)tt * DD], num);
        float rcp;
        asm("rcp.approx.f32 %0, %1;" : "=f"(rcp) : "f"(den));
        cp[(size_t)tt * DD] = __float2half_rn(num * rcp);
    }
}

// =====================================================================
// GEMM 2: out = tanh([ctx,x]·Wc^T + bc); K split ctx(0:1024)/x(1024:2048)
// grid = (d-tiles=16, n-tiles=256)
// =====================================================================
__global__ __launch_bounds__(128, 3)
void gemm_out_mma(const float* __restrict__ bc, float* __restrict__ out)
{
    extern __shared__ char dyn[];
    const int tid = threadIdx.x;
    const int d0 = blockIdx.x * 64;
    const int n0 = blockIdx.y * 128;
    const u32 dynb = smem_u32(dyn);
    const u32 base = (dynb + 1023u) & ~1023u;

    const __half* Bp = g_Wc + (size_t)d0 * K2;

    const LaneCtx cx = make_ctx(tid);
    const LoadOff lo = make_loff(tid, K2);
    float acc[4][4][4];
#pragma unroll
    for (int i = 0; i < 4; i++)
#pragma unroll
        for (int j = 0; j < 4; j++)
#pragma unroll
            for (int q = 0; q < 4; q++) acc[i][j][q] = 0.f;

    auto getA = [&](int ko) -> const __half* {
        return (ko < DD) ? (g_C16 + (size_t)n0 * DD + ko)
                         : (g_X16 + (size_t)n0 * DD + (ko - DD));
    };

    load_stage(base, lo, K2, getA(0), Bp);
    CP_COMMIT();

    const int NCH = K2 / 64;   // 32
    for (int kt = 0; kt < NCH; kt++) {
        if (kt > 0) __syncthreads();
        if (kt + 1 < NCH) {
            const u32 sb2 = base + ((u32)((kt+1) & 1)) * STAGE_B;
            const int ko = (kt + 1) * 64;
            load_stage(sb2, lo, K2, getA(ko), Bp + ko);
            CP_COMMIT();
            CP_WAIT1();
        } else {
            CP_WAIT0();
        }
        __syncthreads();
        mma_chunk(acc, cx, base + ((u32)(kt & 1)) * STAGE_B);
    }

    // epilogue: tanh(acc + bc) -> out
    const int lane = tid & 31;
    const int wm = (tid >> 5) >> 1, wn = (tid >> 5) & 1;
#pragma unroll
    for (int ni = 0; ni < 4; ni++) {
        const int colb = d0 + wn*32 + ni*8 + 2*(lane & 3);
        const float2 bcv = *(const float2*)(bc + colb);
#pragma unroll
        for (int mi = 0; mi < 4; mi++) {
            const int row0 = n0 + wm*64 + mi*16 + (lane >> 2);
            float2 o0, o1;
            o0.x = tanh_acc(acc[mi][ni][0] + bcv.x);
            o0.y = tanh_acc(acc[mi][ni][1] + bcv.y);
            o1.x = tanh_acc(acc[mi][ni][2] + bcv.x);
            o1.y = tanh_acc(acc[mi][ni][3] + bcv.y);
            *(float2*)(out + (size_t)row0 * DD + colb) = o0;
            *(float2*)(out + (size_t)(row0 + 8) * DD + colb) = o1;
        }
    }
}

// =====================================================================
// converters: fp32 -> fp16 (round to nearest)
// =====================================================================
struct __align__(8) hf4 { __half v[4]; };

__device__ __forceinline__ void round4h(const float* __restrict__ src,
                                        __half* __restrict__ dst, int i) {
    float4 v = ((const float4*)src)[i];
    hf4 h;
    h.v[0] = __float2half_rn(v.x); h.v[1] = __float2half_rn(v.y);
    h.v[2] = __float2half_rn(v.z); h.v[3] = __float2half_rn(v.w);
    ((hf4*)dst)[i] = h;
}
__global__ void cvt_x(const float* __restrict__ src) {
    int i = blockIdx.x * blockDim.x + threadIdx.x;
    if (i < NTOK * (DD/4)) round4h(src, g_X16, i);
}
__global__ void cvt_w1(const float* __restrict__ src) {
    int i = blockIdx.x * blockDim.x + threadIdx.x;
    if (i < DD * (DD/4)) round4h(src, g_W1, i);
}
__global__ void cvt_wc(const float* __restrict__ src) {
    int i = blockIdx.x * blockDim.x + threadIdx.x;
    if (i < DD * (K2/4)) round4h(src, g_Wc, i);
}

// =====================================================================
extern "C" void kernel_launch(void* const* d_in, const int* in_sizes, int n_in,
                              void* d_out, int out_size)
{
    const float* x  = (const float*)d_in[0];
    const float* W1 = (const float*)d_in[1];
    const float* b1 = (const float*)d_in[2];
    const float* w2 = (const float*)d_in[3];
    const float* b2 = (const float*)d_in[4];
    const float* Wc = (const float*)d_in[5];
    const float* bc = (const float*)d_in[6];
    float* out = (float*)d_out;

    cudaFuncSetAttribute(gemm_score_mma, cudaFuncAttributeMaxDynamicSharedMemorySize, DYN_B);
    cudaFuncSetAttribute(gemm_out_mma,   cudaFuncAttributeMaxDynamicSharedMemorySize, DYN_B);

    cvt_x <<<(NTOK*(DD/4) + 255)/256, 256>>>(x);
    cvt_w1<<<(DD*(DD/4)   + 255)/256, 256>>>(W1);
    cvt_wc<<<(DD*(K2/4)   + 255)/256, 256>>>(Wc);

    dim3 g1(DD / 64, NTOK / 128);       // (16, 256): e-tiles fast, share A
    gemm_score_mma<<<g1, 128, DYN_B>>>(b1, w2);

    softmax_prep<<<BB, 256>>>(b2);

    dim3 gp(DD / 128, BB, NCHK - 1);
    scan_part<<<gp, 128>>>(x);
    prefP<<<BB, 1024>>>();
    dim3 gf(DD / 128, BB, NCHK);
    scan_final<<<gf, 128>>>(x);

    dim3 g4(K2 / 128, NTOK / 128);      // (16, 256): d-tiles fast
    gemm_out_mma<<<g4, 128, DYN_B>>>(bc, out);
}

// round 17
// speedup vs baseline: 1.3727x; 1.0093x over previous
#include <cuda_runtime.h>
#include <cuda_fp16.h>
#include <math.h>

// Problem constants
#define BB   8
#define TT   4096
#define DD   1024
#define NTOK (BB*TT)          // 32768
#define K2   (2*DD)           // 2048
#define NCHK 8
#define CHKT 512
#define NEB  8                // e-tiles (128 cols each) for score partials

using u32 = unsigned int;
using u64 = unsigned long long;

// ---------------- scratch (static device globals: allowed) ----------------
__device__ float g_spart[NEB * NTOK];
__device__ float g_e[NTOK];
__device__ float g_P[BB * NCHK * DD];     // per-chunk partial num sums
__device__ float g_den0[BB * NCHK];       // exclusive prefix of chunk e-sums
__device__ __half g_X16[(size_t)NTOK * DD];  // X fp16
__device__ __half g_C16[(size_t)NTOK * DD];  // ctx fp16
__device__ __half g_W1[(size_t)DD * DD];     // W1 fp16
__device__ __half g_Wc[(size_t)DD * K2];     // Wc fp16

// ---------------- helpers ----------------
__device__ __forceinline__ u32 smem_u32(const void* p) {
    u32 a;
    asm("{ .reg .u64 t; cvta.to.shared.u64 t, %1; cvt.u32.u64 %0, t; }" : "=r"(a) : "l"(p));
    return a;
}
__device__ __forceinline__ void cp16(u32 dst, const void* src) {
    asm volatile("cp.async.cg.shared.global [%0], [%1], 16;" :: "r"(dst), "l"(src));
}
#define CP_COMMIT() asm volatile("cp.async.commit_group;" ::: "memory")
#define CP_WAIT1()  asm volatile("cp.async.wait_group 1;" ::: "memory")
#define CP_WAIT0()  asm volatile("cp.async.wait_group 0;" ::: "memory")

__device__ __forceinline__ void ldsm4(u32* r, u32 addr) {
    asm volatile("ldmatrix.sync.aligned.m8n8.x4.shared.b16 {%0,%1,%2,%3}, [%4];"
                 : "=r"(r[0]), "=r"(r[1]), "=r"(r[2]), "=r"(r[3]) : "r"(addr));
}
__device__ __forceinline__ void hmma(float* c, const u32* a, u32 b0, u32 b1) {
    asm("mma.sync.aligned.m16n8k16.row.col.f32.f16.f16.f32 "
        "{%0,%1,%2,%3}, {%4,%5,%6,%7}, {%8,%9}, {%0,%1,%2,%3};"
        : "+f"(c[0]), "+f"(c[1]), "+f"(c[2]), "+f"(c[3])
        : "r"(a[0]), "r"(a[1]), "r"(a[2]), "r"(a[3]), "r"(b0), "r"(b1));
}
// accurate fast tanh: 1 - 2/(1+e^{2x})
__device__ __forceinline__ float tanh_acc(float x) {
    float e, r;
    asm("ex2.approx.f32 %0, %1;" : "=f"(e) : "f"(x * 2.885390081777927f));
    asm("rcp.approx.f32 %0, %1;" : "=f"(r) : "f"(e + 1.0f));
    return fmaf(-2.0f, r, 1.0f);
}

// ---------------- tile geometry ----------------
// CTA tile 128(M) x 128(N), K-chunk 64. 4 warps (2x2), warp tile 64x64.
// Warp tile 64x64 halves ldsm crossbar traffic per HMMA vs 64x32:
// smem:tensor cycle ratio drops 1.0 -> 0.75 (SM crossbar was the binder).
// 32KB/stage, 2 stages -> ~66KB dyn smem, 2 CTAs/SM for edge de-phasing.
#define A_TILE   16384                 // 128 x 64 fp16
#define B_TILE   16384                 // 128 x 64 fp16
#define STAGE_B  (A_TILE + B_TILE)     // 32 KB
#define DYN_B    (2*STAGE_B + 1024)

// per-lane fragment addressing constants
struct LaneCtx {
    u32 raoff[4];   // A row offsets per 16-row m tile (warp covers m=64)
    u32 rboff[4];   // B row offsets per 16-row n-pair (warp covers n=64)
    u32 colk[4];    // swizzled column offset per k16
};
__device__ __forceinline__ LaneCtx make_ctx(int tid) {
    LaneCtx cx;
    const int lane = tid & 31;
    const int wm = (tid >> 5) >> 1;        // 0..1
    const int wn = (tid >> 5) & 1;         // 0..1
    const int quad = lane >> 3, r8 = lane & 7;
    const int cb = (quad >> 1) << 4;
    const int rsel = ((quad & 1) << 3) + r8;
    const u32 xsw = (u32)(r8 << 4);
#pragma unroll
    for (int mi = 0; mi < 4; mi++) cx.raoff[mi] = (u32)((wm*64 + mi*16 + rsel) * 128);
#pragma unroll
    for (int p = 0; p < 4; p++)    cx.rboff[p]  = (u32)((wn*64 + p*16 + rsel) * 128);
#pragma unroll
    for (int k = 0; k < 4; k++)    cx.colk[k]   = ((u32)(cb + k*32)) ^ xsw;
    return cx;
}

// load offsets: base + linear stride (SW128 xor invariant under row += 16,
// so smem offsets advance by exactly 16*128 = 2048 bytes per step).
struct LoadOff {
    u32 ag0, bg0, sw0;
};
__device__ __forceinline__ LoadOff make_loff(int tid, int bstride) {
    LoadOff lo;
    const int row = tid >> 3, c8 = (tid & 7) << 3;
    lo.ag0 = (u32)(row * DD + c8);
    lo.bg0 = (u32)(row * bstride + c8);
    u32 off = (u32)(row * 128 + (c8 << 1));
    lo.sw0 = off ^ ((off >> 3) & 0x70u);
    return lo;
}

// A: 128 rows (8 steps of 16), B: 128 rows (8 steps of 16); 128 threads
__device__ __forceinline__ void load_stage(u32 sb2, const LoadOff& lo, int bstride,
                                           const __half* pA, const __half* pB) {
#pragma unroll
    for (int i = 0; i < 8; i++)
        cp16(sb2 + lo.sw0 + (u32)(i*2048), pA + lo.ag0 + i*16*DD);
#pragma unroll
    for (int i = 0; i < 8; i++)
        cp16(sb2 + A_TILE + lo.sw0 + (u32)(i*2048), pB + lo.bg0 + i*16*bstride);
}

// MMA over one resident 64-wide K chunk, warp tile 64x64, single fp16 product.
__device__ __forceinline__ void mma_chunk(float acc[4][8][4], const LaneCtx& cx, u32 stage) {
    const u32 Ab = stage, Bb = stage + A_TILE;
#pragma unroll
    for (int k16 = 0; k16 < 4; k16++) {
        const u32 c = cx.colk[k16];
        u32 b[4][4];
#pragma unroll
        for (int p = 0; p < 4; p++) ldsm4(b[p], Bb + cx.rboff[p] + c);
        u32 a[4][4];
#pragma unroll
        for (int mi = 0; mi < 4; mi++) ldsm4(a[mi], Ab + cx.raoff[mi] + c);
#pragma unroll
        for (int mi = 0; mi < 4; mi++)
#pragma unroll
            for (int ni = 0; ni < 8; ni++) {
                const int p = ni >> 1, s = ni & 1;
                hmma(acc[mi][ni], a[mi], b[p][s], b[p][s+2]);
            }
    }
}

// =====================================================================
// GEMM 1: scores. D[n,e] = X·W1^T; epilogue: spart = sum_e tanh(D+b1)*w2
// grid = (e-tiles=8, n-tiles=256); consecutive blocks share the A tile.
// =====================================================================
__global__ __launch_bounds__(128, 2)
void gemm_score_mma(const float* __restrict__ b1, const float* __restrict__ w2)
{
    extern __shared__ char dyn[];
    __shared__ float red[128][2];
    const int tid = threadIdx.x;
    const int e0 = blockIdx.x * 128;
    const int n0 = blockIdx.y * 128;
    const u32 dynb = smem_u32(dyn);
    const u32 base = (dynb + 1023u) & ~1023u;

    const __half* Ap = g_X16 + (size_t)n0 * DD;
    const __half* Bp = g_W1  + (size_t)e0 * DD;

    const LaneCtx cx = make_ctx(tid);
    const LoadOff lo = make_loff(tid, DD);
    float acc[4][8][4];
#pragma unroll
    for (int i = 0; i < 4; i++)
#pragma unroll
        for (int j = 0; j < 8; j++)
#pragma unroll
            for (int q = 0; q < 4; q++) acc[i][j][q] = 0.f;

    load_stage(base, lo, DD, Ap, Bp);
    CP_COMMIT();

    const int NCH = DD / 64;   // 16
    for (int kt = 0; kt < NCH; kt++) {
        if (kt > 0) __syncthreads();
        if (kt + 1 < NCH) {
            const u32 sb2 = base + ((u32)((kt+1) & 1)) * STAGE_B;
            const int ko = (kt + 1) * 64;
            load_stage(sb2, lo, DD, Ap + ko, Bp + ko);
            CP_COMMIT();
            CP_WAIT1();
        } else {
            CP_WAIT0();
        }
        __syncthreads();
        mma_chunk(acc, cx, base + ((u32)(kt & 1)) * STAGE_B);
    }

    // epilogue: tanh(D+b1)*w2, reduce over the CTA's 128 e-cols
    const int lane = tid & 31;
    const int wm = (tid >> 5) >> 1, wn = (tid >> 5) & 1;
    float b1x[8], b1y[8], w2x[8], w2y[8];
#pragma unroll
    for (int ni = 0; ni < 8; ni++) {
        const int col = e0 + wn*64 + ni*8 + 2*(lane & 3);
        float2 bv = *(const float2*)(b1 + col);
        float2 wv = *(const float2*)(w2 + col);
        b1x[ni] = bv.x; b1y[ni] = bv.y; w2x[ni] = wv.x; w2y[ni] = wv.y;
    }
#pragma unroll
    for (int mi = 0; mi < 4; mi++)
#pragma unroll
        for (int h2 = 0; h2 < 2; h2++) {
            float s = 0.f;
#pragma unroll
            for (int ni = 0; ni < 8; ni++) {
                s += tanh_acc(acc[mi][ni][h2*2+0] + b1x[ni]) * w2x[ni];
                s += tanh_acc(acc[mi][ni][h2*2+1] + b1y[ni]) * w2y[ni];
            }
            s += __shfl_xor_sync(0xffffffffu, s, 1);
            s += __shfl_xor_sync(0xffffffffu, s, 2);
            if ((lane & 3) == 0)
                red[wm*64 + mi*16 + h2*8 + (lane >> 2)][wn] = s;
        }
    __syncthreads();
    g_spart[(size_t)blockIdx.x * NTOK + n0 + tid] = red[tid][0] + red[tid][1];
}

// =====================================================================
// Kernel 2: per-batch max + e = exp(s + b2 - m); also per-chunk e sums
// =====================================================================
__global__ void softmax_prep(const float* __restrict__ b2)
{
    const int b = blockIdx.x, tid = threadIdx.x;   // 256 threads
    const int lane = tid & 31;
    float vloc[16];
    float mx = -INFINITY;
    const float b2v = b2[0];
#pragma unroll
    for (int i = 0; i < 16; i++) {
        int t = tid + i * 256;
        float s = 0.f;
#pragma unroll
        for (int eb = 0; eb < NEB; eb++) s += g_spart[(size_t)eb * NTOK + b * TT + t];
        s += b2v;
        vloc[i] = s;
        mx = fmaxf(mx, s);
    }
    __shared__ float sm[256];
    __shared__ float dsum[NCHK];
    sm[tid] = mx;
    if (tid < NCHK) dsum[tid] = 0.f;
    __syncthreads();
    for (int off = 128; off > 0; off >>= 1) {
        if (tid < off) sm[tid] = fmaxf(sm[tid], sm[tid + off]);
        __syncthreads();
    }
    float m = sm[0];
    float eloc[16];
#pragma unroll
    for (int i = 0; i < 16; i++) {
        int t = tid + i * 256;
        eloc[i] = expf(vloc[i] - m);
        g_e[b * TT + t] = eloc[i];
    }
#pragma unroll
    for (int c = 0; c < NCHK; c++) {
        float v = eloc[2*c] + eloc[2*c+1];
#pragma unroll
        for (int off = 16; off > 0; off >>= 1)
            v += __shfl_xor_sync(0xffffffffu, v, off);
        if (lane == 0) atomicAdd(&dsum[c], v);
    }
    __syncthreads();
    if (tid == 0) {
        float run = 0.f;
#pragma unroll
        for (int c = 0; c < NCHK; c++) { g_den0[b * NCHK + c] = run; run += dsum[c]; }
    }
}

// =====================================================================
// Scan pass A: per-chunk partial sums  P[b,chunk,d] = sum_{t in chunk} e*x
// =====================================================================
__global__ void scan_part(const float* __restrict__ X)
{
    const int b = blockIdx.y, chunk = blockIdx.z;
    const int d = blockIdx.x * 128 + threadIdx.x;
    const float* xb = X + (size_t)b * TT * DD + (size_t)chunk * CHKT * DD + d;
    __shared__ float es[CHKT];
#pragma unroll
    for (int i = 0; i < CHKT/128; i++)
        es[threadIdx.x + i*128] = g_e[b * TT + chunk * CHKT + threadIdx.x + i*128];
    __syncthreads();
    float P = 0.f;
#pragma unroll 8
    for (int tt = 0; tt < CHKT; ++tt)
        P = fmaf(es[tt], xb[(size_t)tt * DD], P);
    g_P[(b * NCHK + chunk) * DD + d] = P;
}

// Exclusive prefix of P over chunks (in place). grid BB, 1024 threads.
__global__ void prefP()
{
    const int b = blockIdx.x, d = threadIdx.x;
    float run = 0.f;
#pragma unroll
    for (int c = 0; c < NCHK; c++) {
        int idx = (b * NCHK + c) * DD + d;
        float t = (c < NCHK-1) ? g_P[idx] : 0.f;
        g_P[idx] = run;
        run += t;
    }
}

// =====================================================================
// Scan pass B: local cumsum + prefix offsets; emits ctx as fp16.
// =====================================================================
__global__ void scan_final(const float* __restrict__ X)
{
    const int b = blockIdx.y, chunk = blockIdx.z;
    const int d = blockIdx.x * 128 + threadIdx.x;
    const size_t rowoff = (size_t)b * TT * DD + (size_t)chunk * CHKT * DD + d;
    const float* xb = X + rowoff;
    __half* cp = g_C16 + rowoff;

    __shared__ float es[CHKT];
#pragma unroll
    for (int i = 0; i < CHKT/128; i++)
        es[threadIdx.x + i*128] = g_e[b * TT + chunk * CHKT + threadIdx.x + i*128];
    __syncthreads();

    float den = g_den0[b * NCHK + chunk];
    float num = g_P[(b * NCHK + chunk) * DD + d];
#pragma unroll 8
    for (int tt = 0; tt < CHKT; ++tt) {
        float ev = es[tt];
        den += ev;
        num = fmaf(ev, xb[(size_t)tt * DD], num);
        float rcp;
        asm("rcp.approx.f32 %0, %1;" : "=f"(rcp) : "f"(den));
        cp[(size_t)tt * DD] = __float2half_rn(num * rcp);
    }
}

// =====================================================================
// GEMM 2: out = tanh([ctx,x]·Wc^T + bc); K split ctx(0:1024)/x(1024:2048)
// grid = (d-tiles=8, n-tiles=256)
// =====================================================================
__global__ __launch_bounds__(128, 2)
void gemm_out_mma(const float* __restrict__ bc, float* __restrict__ out)
{
    extern __shared__ char dyn[];
    const int tid = threadIdx.x;
    const int d0 = blockIdx.x * 128;
    const int n0 = blockIdx.y * 128;
    const u32 dynb = smem_u32(dyn);
    const u32 base = (dynb + 1023u) & ~1023u;

    const __half* Bp = g_Wc + (size_t)d0 * K2;

    const LaneCtx cx = make_ctx(tid);
    const LoadOff lo = make_loff(tid, K2);
    float acc[4][8][4];
#pragma unroll
    for (int i = 0; i < 4; i++)
#pragma unroll
        for (int j = 0; j < 8; j++)
#pragma unroll
            for (int q = 0; q < 4; q++) acc[i][j][q] = 0.f;

    auto getA = [&](int ko) -> const __half* {
        return (ko < DD) ? (g_C16 + (size_t)n0 * DD + ko)
                         : (g_X16 + (size_t)n0 * DD + (ko - DD));
    };

    load_stage(base, lo, K2, getA(0), Bp);
    CP_COMMIT();

    const int NCH = K2 / 64;   // 32
    for (int kt = 0; kt < NCH; kt++) {
        if (kt > 0) __syncthreads();
        if (kt + 1 < NCH) {
            const u32 sb2 = base + ((u32)((kt+1) & 1)) * STAGE_B;
            const int ko = (kt + 1) * 64;
            load_stage(sb2, lo, K2, getA(ko), Bp + ko);
            CP_COMMIT();
            CP_WAIT1();
        } else {
            CP_WAIT0();
        }
        __syncthreads();
        mma_chunk(acc, cx, base + ((u32)(kt & 1)) * STAGE_B);
    }

    // epilogue: tanh(acc + bc) -> out
    const int lane = tid & 31;
    const int wm = (tid >> 5) >> 1, wn = (tid >> 5) & 1;
#pragma unroll
    for (int ni = 0; ni < 8; ni++) {
        const int colb = d0 + wn*64 + ni*8 + 2*(lane & 3);
        const float2 bcv = *(const float2*)(bc + colb);
#pragma unroll
        for (int mi = 0; mi < 4; mi++) {
            const int row0 = n0 + wm*64 + mi*16 + (lane >> 2);
            float2 o0, o1;
            o0.x = tanh_acc(acc[mi][ni][0] + bcv.x);
            o0.y = tanh_acc(acc[mi][ni][1] + bcv.y);
            o1.x = tanh_acc(acc[mi][ni][2] + bcv.x);
            o1.y = tanh_acc(acc[mi][ni][3] + bcv.y);
            *(float2*)(out + (size_t)row0 * DD + colb) = o0;
            *(float2*)(out + (size_t)(row0 + 8) * DD + colb) = o1;
        }
    }
}

// =====================================================================
// converters: fp32 -> fp16 (round to nearest)
// =====================================================================
struct __align__(8) hf4 { __half v[4]; };

__device__ __forceinline__ void round4h(const float* __restrict__ src,
                                        __half* __restrict__ dst, int i) {
    float4 v = ((const float4*)src)[i];
    hf4 h;
    h.v[0] = __float2half_rn(v.x); h.v[1] = __float2half_rn(v.y);
    h.v[2] = __float2half_rn(v.z); h.v[3] = __float2half_rn(v.w);
    ((hf4*)dst)[i] = h;
}
__global__ void cvt_x(const float* __restrict__ src) {
    int i = blockIdx.x * blockDim.x + threadIdx.x;
    if (i < NTOK * (DD/4)) round4h(src, g_X16, i);
}
__global__ void cvt_w1(const float* __restrict__ src) {
    int i = blockIdx.x * blockDim.x + threadIdx.x;
    if (i < DD * (DD/4)) round4h(src, g_W1, i);
}
__global__ void cvt_wc(const float* __restrict__ src) {
    int i = blockIdx.x * blockDim.x + threadIdx.x;
    if (i < DD * (K2/4)) round4h(src, g_Wc, i);
}

// =====================================================================
extern "C" void kernel_launch(void* const* d_in, const int* in_sizes, int n_in,
                              void* d_out, int out_size)
{
    const float* x  = (const float*)d_in[0];
    const float* W1 = (const float*)d_in[1];
    const float* b1 = (const float*)d_in[2];
    const float* w2 = (const float*)d_in[3];
    const float* b2 = (const float*)d_in[4];
    const float* Wc = (const float*)d_in[5];
    const float* bc = (const float*)d_in[6];
    float* out = (float*)d_out;

    cudaFuncSetAttribute(gemm_score_mma, cudaFuncAttributeMaxDynamicSharedMemorySize, DYN_B);
    cudaFuncSetAttribute(gemm_out_mma,   cudaFuncAttributeMaxDynamicSharedMemorySize, DYN_B);

    cvt_x <<<(NTOK*(DD/4) + 255)/256, 256>>>(x);
    cvt_w1<<<(DD*(DD/4)   + 255)/256, 256>>>(W1);
    cvt_wc<<<(DD*(K2/4)   + 255)/256, 256>>>(Wc);

    dim3 g1(DD / 128, NTOK / 128);      // (8, 256): e-tiles fast, share A
    gemm_score_mma<<<g1, 128, DYN_B>>>(b1, w2);

    softmax_prep<<<BB, 256>>>(b2);

    dim3 gp(DD / 128, BB, NCHK - 1);
    scan_part<<<gp, 128>>>(x);
    prefP<<<BB, 1024>>>();
    dim3 gf(DD / 128, BB, NCHK);
    scan_final<<<gf, 128>>>(x);

    dim3 g4(DD / 128, NTOK / 128);      // (8, 256): d-tiles fast
    gemm_out_mma<<<g4, 128, DYN_B>>>(bc, out);
}